// round 3
// baseline (speedup 1.0000x reference)
#include <cuda_runtime.h>
#include <math.h>

// Problem constants
#define CB   4
#define CS   2048
#define CD   1024
#define CH   8
#define CHID 4096

// ---------------------------------------------------------------------------
// Scratch (device globals; no allocations allowed)
// ---------------------------------------------------------------------------
// Layouts:
//  g_Q/g_K/g_V : [H][B][S][D]
//  g_SC        : [H][B][S][S]   (scores, then attn in-place)
//  g_ZC        : [B][S][H][D]   (head-concat of attn@V)
//  g_AO        : [B*S][D]       (attn out / ffn out reuse)
//  g_Z1        : [B*S][D]       (post first LN)
//  g_Y1/g_Y2   : [B*S][HID]
__device__ float g_Q [(size_t)CH * CB * CS * CD];
__device__ float g_K [(size_t)CH * CB * CS * CD];
__device__ float g_V [(size_t)CH * CB * CS * CD];
__device__ float g_SC[(size_t)CH * CB * CS * CS];
__device__ float g_ZC[(size_t)CB * CS * CH * CD];
__device__ float g_AO[(size_t)CB * CS * CD];
__device__ float g_Z1[(size_t)CB * CS * CD];
__device__ float g_Y1[(size_t)CB * CS * CHID];
__device__ float g_Y2[(size_t)CB * CS * CHID];

// ---------------------------------------------------------------------------
// Generic batched SGEMM: C = alpha * A * op(B) (+bias) (+relu)
//   A: [M,K] row-major (lda), op(B)=B [K,N] (ldb) or B^T with B [N,K] (ldb)
//   Batch z: A += z*sA, B += z*sB, C += (z/cdiv)*cs1 + (z%cdiv)*cs2
//   Tile: 128x128x8, 256 threads, 8x8 per-thread microtile, reg prefetch.
//   All M,N divisible by 128 and K by 8 for these shapes (no guards).
// ---------------------------------------------------------------------------
template<bool TRANSB, bool RELU, bool BIAS>
__global__ void __launch_bounds__(256, 2)
gemm_k(const float* __restrict__ A, const float* __restrict__ B,
       float* __restrict__ C, const float* __restrict__ bias,
       int M, int N, int K, int lda, int ldb, int ldc,
       long long sA, long long sB, long long cs1, long long cs2, int cdiv,
       float alpha)
{
    __shared__ float As[8][128];
    __shared__ float Bs[8][128];

    const int z = blockIdx.z;
    A += (long long)z * sA;
    B += (long long)z * sB;
    C += (long long)(z / cdiv) * cs1 + (long long)(z % cdiv) * cs2;

    const int m0 = blockIdx.y * 128;
    const int n0 = blockIdx.x * 128;
    const int tid = threadIdx.x;

    // loader indices (A always; B in TRANSB mode uses same pattern)
    const int lrow = tid >> 1;            // 0..127
    const int lcol = (tid & 1) * 4;       // 0 or 4
    // B loader, NN mode
    const int bkr = tid >> 5;             // 0..7
    const int bnc = (tid & 31) * 4;       // 0..124

    const int ty = tid >> 4;              // 0..15  -> rows ty*8..ty*8+7
    const int tx = tid & 15;              // 0..15  -> cols tx*8..tx*8+7

    const float* Aptr = A + (long long)(m0 + lrow) * lda + lcol;
    const float* Bptr = TRANSB
        ? (B + (long long)(n0 + lrow) * ldb + lcol)
        : (B + (long long)bkr * ldb + n0 + bnc);

    float acc[8][8];
    #pragma unroll
    for (int i = 0; i < 8; i++)
        #pragma unroll
        for (int j = 0; j < 8; j++) acc[i][j] = 0.f;

    const int nt = K >> 3;
    float4 pa = *(const float4*)(Aptr);
    float4 pb = *(const float4*)(Bptr);

    for (int kt = 0; kt < nt; kt++) {
        __syncthreads();
        As[lcol + 0][lrow] = pa.x; As[lcol + 1][lrow] = pa.y;
        As[lcol + 2][lrow] = pa.z; As[lcol + 3][lrow] = pa.w;
        if (TRANSB) {
            Bs[lcol + 0][lrow] = pb.x; Bs[lcol + 1][lrow] = pb.y;
            Bs[lcol + 2][lrow] = pb.z; Bs[lcol + 3][lrow] = pb.w;
        } else {
            *(float4*)&Bs[bkr][bnc] = pb;
        }
        __syncthreads();
        if (kt + 1 < nt) {   // prefetch next tile into registers
            pa = *(const float4*)(Aptr + (long long)(kt + 1) * 8);
            pb = TRANSB
               ? *(const float4*)(Bptr + (long long)(kt + 1) * 8)
               : *(const float4*)(Bptr + (long long)(kt + 1) * 8 * ldb);
        }
        #pragma unroll
        for (int kk = 0; kk < 8; kk++) {
            float a[8], b[8];
            #pragma unroll
            for (int i = 0; i < 8; i++) a[i] = As[kk][ty * 8 + i];
            #pragma unroll
            for (int j = 0; j < 8; j++) b[j] = Bs[kk][tx * 8 + j];
            #pragma unroll
            for (int i = 0; i < 8; i++)
                #pragma unroll
                for (int j = 0; j < 8; j++)
                    acc[i][j] = fmaf(a[i], b[j], acc[i][j]);
        }
    }

    // epilogue
    #pragma unroll
    for (int i = 0; i < 8; i++) {
        const int m = m0 + ty * 8 + i;
        float* cr = C + (long long)m * ldc + n0 + tx * 8;
        #pragma unroll
        for (int j = 0; j < 8; j += 4) {
            float4 v;
            v.x = acc[i][j + 0] * alpha;
            v.y = acc[i][j + 1] * alpha;
            v.z = acc[i][j + 2] * alpha;
            v.w = acc[i][j + 3] * alpha;
            if (BIAS) {
                const float* bp = bias + n0 + tx * 8 + j;
                v.x += bp[0]; v.y += bp[1]; v.z += bp[2]; v.w += bp[3];
            }
            if (RELU) {
                v.x = fmaxf(v.x, 0.f); v.y = fmaxf(v.y, 0.f);
                v.z = fmaxf(v.z, 0.f); v.w = fmaxf(v.w, 0.f);
            }
            *(float4*)(cr + j) = v;
        }
    }
}

// ---------------------------------------------------------------------------
// Row softmax over last dim (CS = 2048), in place. One block per row.
// ---------------------------------------------------------------------------
__global__ void __launch_bounds__(256)
softmax_k(float* __restrict__ sc)
{
    const long long row = blockIdx.x;
    float* p = sc + row * (long long)CS;
    const int tid = threadIdx.x;
    __shared__ float sm[8];

    float v[8];
    float mx = -3.4e38f;
    #pragma unroll
    for (int i = 0; i < 8; i++) { v[i] = p[tid + i * 256]; mx = fmaxf(mx, v[i]); }

    #pragma unroll
    for (int o = 16; o; o >>= 1) mx = fmaxf(mx, __shfl_xor_sync(0xffffffffu, mx, o));
    if ((tid & 31) == 0) sm[tid >> 5] = mx;
    __syncthreads();
    if (tid < 32) {
        float t = (tid < 8) ? sm[tid] : -3.4e38f;
        #pragma unroll
        for (int o = 4; o; o >>= 1) t = fmaxf(t, __shfl_xor_sync(0xffffffffu, t, o));
        if (tid == 0) sm[0] = t;
    }
    __syncthreads();
    mx = sm[0];
    __syncthreads();

    float s = 0.f;
    #pragma unroll
    for (int i = 0; i < 8; i++) { v[i] = __expf(v[i] - mx); s += v[i]; }

    #pragma unroll
    for (int o = 16; o; o >>= 1) s += __shfl_xor_sync(0xffffffffu, s, o);
    if ((tid & 31) == 0) sm[tid >> 5] = s;
    __syncthreads();
    if (tid < 32) {
        float t = (tid < 8) ? sm[tid] : 0.f;
        #pragma unroll
        for (int o = 4; o; o >>= 1) t += __shfl_xor_sync(0xffffffffu, t, o);
        if (tid == 0) sm[0] = t;
    }
    __syncthreads();
    const float inv = 1.0f / sm[0];

    #pragma unroll
    for (int i = 0; i < 8; i++) p[tid + i * 256] = v[i] * inv;
}

// ---------------------------------------------------------------------------
// out = LayerNorm(x + y) * g + b, row length CD = 1024. One block per row.
// ---------------------------------------------------------------------------
__global__ void __launch_bounds__(256)
add_ln_k(const float* __restrict__ x, const float* __restrict__ y,
         const float* __restrict__ g, const float* __restrict__ b,
         float* __restrict__ out)
{
    const long long row = blockIdx.x;
    const float* px = x + row * (long long)CD;
    const float* py = y + row * (long long)CD;
    float* po = out + row * (long long)CD;
    const int tid = threadIdx.x;
    __shared__ float sm[16];

    float v[4];
    float s = 0.f, s2 = 0.f;
    #pragma unroll
    for (int i = 0; i < 4; i++) {
        float t = px[tid + i * 256] + py[tid + i * 256];
        v[i] = t; s += t; s2 += t * t;
    }
    #pragma unroll
    for (int o = 16; o; o >>= 1) {
        s  += __shfl_xor_sync(0xffffffffu, s,  o);
        s2 += __shfl_xor_sync(0xffffffffu, s2, o);
    }
    if ((tid & 31) == 0) { sm[tid >> 5] = s; sm[8 + (tid >> 5)] = s2; }
    __syncthreads();
    if (tid < 32) {
        float t  = (tid < 8) ? sm[tid]     : 0.f;
        float t2 = (tid < 8) ? sm[8 + tid] : 0.f;
        #pragma unroll
        for (int o = 4; o; o >>= 1) {
            t  += __shfl_xor_sync(0xffffffffu, t,  o);
            t2 += __shfl_xor_sync(0xffffffffu, t2, o);
        }
        if (tid == 0) { sm[0] = t; sm[8] = t2; }
    }
    __syncthreads();
    const float mean = sm[0] * (1.0f / CD);
    const float var  = sm[8] * (1.0f / CD) - mean * mean;
    const float rs = rsqrtf(var + 1e-5f);

    #pragma unroll
    for (int i = 0; i < 4; i++) {
        const int c = tid + i * 256;
        po[c] = (v[i] - mean) * rs * g[c] + b[c];
    }
}

// ---------------------------------------------------------------------------
// kernel_launch
// ---------------------------------------------------------------------------
extern "C" void kernel_launch(void* const* d_in, const int* in_sizes, int n_in,
                              void* d_out, int out_size)
{
    const float* x   = (const float*)d_in[0];
    const float* Wq  = (const float*)d_in[1];
    const float* Wk  = (const float*)d_in[2];
    const float* Wv  = (const float*)d_in[3];
    const float* Wo  = (const float*)d_in[4];
    const float* bo  = (const float*)d_in[5];
    const float* w1  = (const float*)d_in[6];
    const float* b1  = (const float*)d_in[7];
    const float* w2  = (const float*)d_in[8];
    const float* b2  = (const float*)d_in[9];
    const float* w3  = (const float*)d_in[10];
    const float* b3  = (const float*)d_in[11];
    const float* w4  = (const float*)d_in[12];
    const float* b4  = (const float*)d_in[13];
    const float* g1  = (const float*)d_in[14];
    const float* be1 = (const float*)d_in[15];
    const float* g2  = (const float*)d_in[16];
    const float* be2 = (const float*)d_in[17];
    float* out = (float*)d_out;

    float *Q, *Kp, *V, *SC, *ZC, *AO, *Z1, *Y1, *Y2;
    cudaGetSymbolAddress((void**)&Q,  g_Q);
    cudaGetSymbolAddress((void**)&Kp, g_K);
    cudaGetSymbolAddress((void**)&V,  g_V);
    cudaGetSymbolAddress((void**)&SC, g_SC);
    cudaGetSymbolAddress((void**)&ZC, g_ZC);
    cudaGetSymbolAddress((void**)&AO, g_AO);
    cudaGetSymbolAddress((void**)&Z1, g_Z1);
    cudaGetSymbolAddress((void**)&Y1, g_Y1);
    cudaGetSymbolAddress((void**)&Y2, g_Y2);

    const int MT = CB * CS;                 // 8192 tokens
    const long long HBD = (long long)CB * CS * CD;   // per-head Q/K/V stride
    const long long SD  = (long long)CS * CD;
    const long long SS  = (long long)CS * CS;

    // 1-3. QKV projections: X[8192,1024] x W[h][1024,1024] -> [h][8192,1024]
    {
        dim3 grid(CD / 128, MT / 128, CH);
        gemm_k<false, false, false><<<grid, 256>>>(x, Wq, Q, nullptr,
            MT, CD, CD, CD, CD, CD, 0, (long long)CD * CD, HBD, 0, 1, 1.0f);
        gemm_k<false, false, false><<<grid, 256>>>(x, Wk, Kp, nullptr,
            MT, CD, CD, CD, CD, CD, 0, (long long)CD * CD, HBD, 0, 1, 1.0f);
        gemm_k<false, false, false><<<grid, 256>>>(x, Wv, V, nullptr,
            MT, CD, CD, CD, CD, CD, 0, (long long)CD * CD, HBD, 0, 1, 1.0f);
    }

    // 4. scores = Q K^T * (1/32), per (h,b): [2048,1024] x [2048,1024]^T
    {
        dim3 grid(CS / 128, CS / 128, CH * CB);
        gemm_k<true, false, false><<<grid, 256>>>(Q, Kp, SC, nullptr,
            CS, CS, CD, CD, CD, CS, SD, SD, SS, 0, 1, 0.03125f);
    }

    // 5. softmax over rows (H*B*S rows of length S)
    softmax_k<<<CH * CB * CS, 256>>>(SC);

    // 6. Z = attn @ V, written in head-concat layout ZC[b][s][h*D+e]
    //    z index = h*CB + b ; C offset = (z/CB)*D + (z%CB)*(S*H*D), ldc = H*D
    {
        dim3 grid(CD / 128, CS / 128, CH * CB);
        gemm_k<false, false, false><<<grid, 256>>>(SC, V, ZC, nullptr,
            CS, CD, CS, CS, CD, CH * CD, SS, SD,
            (long long)CD, (long long)CS * CH * CD, CB, 1.0f);
    }

    // 7. attn_out = ZC[8192, 8192] @ Wo[8192,1024] + bo
    {
        dim3 grid(CD / 128, MT / 128, 1);
        gemm_k<false, false, true><<<grid, 256>>>(ZC, Wo, AO, bo,
            MT, CD, CH * CD, CH * CD, CD, CD, 0, 0, 0, 0, 1, 1.0f);
    }

    // 8. Z1 = LN(x + attn_out)
    add_ln_k<<<MT, 256>>>(x, AO, g1, be1, Z1);

    // 9-12. FFN
    {
        dim3 g1d(CHID / 128, MT / 128, 1);
        gemm_k<false, true, true><<<g1d, 256>>>(Z1, w1, Y1, b1,
            MT, CHID, CD, CD, CHID, CHID, 0, 0, 0, 0, 1, 1.0f);
        gemm_k<false, true, true><<<g1d, 256>>>(Y1, w2, Y2, b2,
            MT, CHID, CHID, CHID, CHID, CHID, 0, 0, 0, 0, 1, 1.0f);
        gemm_k<false, true, true><<<g1d, 256>>>(Y2, w3, Y1, b3,
            MT, CHID, CHID, CHID, CHID, CHID, 0, 0, 0, 0, 1, 1.0f);
        dim3 g4(CD / 128, MT / 128, 1);
        gemm_k<false, false, true><<<g4, 256>>>(Y1, w4, AO, b4,
            MT, CD, CHID, CHID, CD, CD, 0, 0, 0, 0, 1, 1.0f);
    }

    // 13. out = LN(Z1 + ffn_out)
    add_ln_k<<<MT, 256>>>(Z1, AO, g2, be2, out);
}

// round 4
// speedup vs baseline: 1.0010x; 1.0010x over previous
#include <cuda_runtime.h>
#include <math.h>

// Problem constants
#define CB   4
#define CS   2048
#define CD   1024
#define CH   8
#define CHID 4096

// ---------------------------------------------------------------------------
// Scratch (device globals; no allocations allowed)
// ---------------------------------------------------------------------------
// Layouts:
//  g_Q/g_K/g_V : [H][B][S][D]
//  g_SC        : [H][B][S][S]   (scores, then attn in-place)
//  g_ZC        : [B][S][H][D]   (head-concat of attn@V)
//  g_AO        : [B*S][D]       (attn out / ffn out reuse)
//  g_Z1        : [B*S][D]       (post first LN)
//  g_Y1/g_Y2   : [B*S][HID]
__device__ float g_Q [(size_t)CH * CB * CS * CD];
__device__ float g_K [(size_t)CH * CB * CS * CD];
__device__ float g_V [(size_t)CH * CB * CS * CD];
__device__ float g_SC[(size_t)CH * CB * CS * CS];
__device__ float g_ZC[(size_t)CB * CS * CH * CD];
__device__ float g_AO[(size_t)CB * CS * CD];
__device__ float g_Z1[(size_t)CB * CS * CD];
__device__ float g_Y1[(size_t)CB * CS * CHID];
__device__ float g_Y2[(size_t)CB * CS * CHID];

// ---------------------------------------------------------------------------
// Generic batched SGEMM: C = alpha * A * op(B) (+bias) (+relu)
//   A: [M,K] row-major (lda), op(B)=B [K,N] (ldb) or B^T with B [N,K] (ldb)
//   Batch z: A += z*sA, B += z*sB, C += (z/cdiv)*cs1 + (z%cdiv)*cs2
//   Tile: 128x128x8, 256 threads, 8x8 per-thread microtile, reg prefetch.
//   All M,N divisible by 128 and K by 8 for these shapes (no guards).
// ---------------------------------------------------------------------------
template<bool TRANSB, bool RELU, bool BIAS>
__global__ void __launch_bounds__(256, 2)
gemm_k(const float* __restrict__ A, const float* __restrict__ B,
       float* __restrict__ C, const float* __restrict__ bias,
       int M, int N, int K, int lda, int ldb, int ldc,
       long long sA, long long sB, long long cs1, long long cs2, int cdiv,
       float alpha)
{
    __shared__ float As[8][128];
    __shared__ float Bs[8][128];

    const int z = blockIdx.z;
    A += (long long)z * sA;
    B += (long long)z * sB;
    C += (long long)(z / cdiv) * cs1 + (long long)(z % cdiv) * cs2;

    const int m0 = blockIdx.y * 128;
    const int n0 = blockIdx.x * 128;
    const int tid = threadIdx.x;

    // loader indices (A always; B in TRANSB mode uses same pattern)
    const int lrow = tid >> 1;            // 0..127
    const int lcol = (tid & 1) * 4;       // 0 or 4
    // B loader, NN mode
    const int bkr = tid >> 5;             // 0..7
    const int bnc = (tid & 31) * 4;       // 0..124

    const int ty = tid >> 4;              // 0..15  -> rows ty*8..ty*8+7
    const int tx = tid & 15;              // 0..15  -> cols tx*8..tx*8+7

    const float* Aptr = A + (long long)(m0 + lrow) * lda + lcol;
    const float* Bptr = TRANSB
        ? (B + (long long)(n0 + lrow) * ldb + lcol)
        : (B + (long long)bkr * ldb + n0 + bnc);

    float acc[8][8];
    #pragma unroll
    for (int i = 0; i < 8; i++)
        #pragma unroll
        for (int j = 0; j < 8; j++) acc[i][j] = 0.f;

    const int nt = K >> 3;
    float4 pa = *(const float4*)(Aptr);
    float4 pb = *(const float4*)(Bptr);

    for (int kt = 0; kt < nt; kt++) {
        __syncthreads();
        As[lcol + 0][lrow] = pa.x; As[lcol + 1][lrow] = pa.y;
        As[lcol + 2][lrow] = pa.z; As[lcol + 3][lrow] = pa.w;
        if (TRANSB) {
            Bs[lcol + 0][lrow] = pb.x; Bs[lcol + 1][lrow] = pb.y;
            Bs[lcol + 2][lrow] = pb.z; Bs[lcol + 3][lrow] = pb.w;
        } else {
            *(float4*)&Bs[bkr][bnc] = pb;
        }
        __syncthreads();
        if (kt + 1 < nt) {   // prefetch next tile into registers
            pa = *(const float4*)(Aptr + (long long)(kt + 1) * 8);
            pb = TRANSB
               ? *(const float4*)(Bptr + (long long)(kt + 1) * 8)
               : *(const float4*)(Bptr + (long long)(kt + 1) * 8 * ldb);
        }
        #pragma unroll
        for (int kk = 0; kk < 8; kk++) {
            float a[8], b[8];
            #pragma unroll
            for (int i = 0; i < 8; i++) a[i] = As[kk][ty * 8 + i];
            #pragma unroll
            for (int j = 0; j < 8; j++) b[j] = Bs[kk][tx * 8 + j];
            #pragma unroll
            for (int i = 0; i < 8; i++)
                #pragma unroll
                for (int j = 0; j < 8; j++)
                    acc[i][j] = fmaf(a[i], b[j], acc[i][j]);
        }
    }

    // epilogue
    #pragma unroll
    for (int i = 0; i < 8; i++) {
        const int m = m0 + ty * 8 + i;
        float* cr = C + (long long)m * ldc + n0 + tx * 8;
        #pragma unroll
        for (int j = 0; j < 8; j += 4) {
            float4 v;
            v.x = acc[i][j + 0] * alpha;
            v.y = acc[i][j + 1] * alpha;
            v.z = acc[i][j + 2] * alpha;
            v.w = acc[i][j + 3] * alpha;
            if (BIAS) {
                const float* bp = bias + n0 + tx * 8 + j;
                v.x += bp[0]; v.y += bp[1]; v.z += bp[2]; v.w += bp[3];
            }
            if (RELU) {
                v.x = fmaxf(v.x, 0.f); v.y = fmaxf(v.y, 0.f);
                v.z = fmaxf(v.z, 0.f); v.w = fmaxf(v.w, 0.f);
            }
            *(float4*)(cr + j) = v;
        }
    }
}

// ---------------------------------------------------------------------------
// Row softmax over last dim (CS = 2048), in place. One block per row.
// ---------------------------------------------------------------------------
__global__ void __launch_bounds__(256)
softmax_k(float* __restrict__ sc)
{
    const long long row = blockIdx.x;
    float* p = sc + row * (long long)CS;
    const int tid = threadIdx.x;
    __shared__ float sm[8];

    float v[8];
    float mx = -3.4e38f;
    #pragma unroll
    for (int i = 0; i < 8; i++) { v[i] = p[tid + i * 256]; mx = fmaxf(mx, v[i]); }

    #pragma unroll
    for (int o = 16; o; o >>= 1) mx = fmaxf(mx, __shfl_xor_sync(0xffffffffu, mx, o));
    if ((tid & 31) == 0) sm[tid >> 5] = mx;
    __syncthreads();
    if (tid < 32) {
        float t = (tid < 8) ? sm[tid] : -3.4e38f;
        #pragma unroll
        for (int o = 4; o; o >>= 1) t = fmaxf(t, __shfl_xor_sync(0xffffffffu, t, o));
        if (tid == 0) sm[0] = t;
    }
    __syncthreads();
    mx = sm[0];
    __syncthreads();

    float s = 0.f;
    #pragma unroll
    for (int i = 0; i < 8; i++) { v[i] = __expf(v[i] - mx); s += v[i]; }

    #pragma unroll
    for (int o = 16; o; o >>= 1) s += __shfl_xor_sync(0xffffffffu, s, o);
    if ((tid & 31) == 0) sm[tid >> 5] = s;
    __syncthreads();
    if (tid < 32) {
        float t = (tid < 8) ? sm[tid] : 0.f;
        #pragma unroll
        for (int o = 4; o; o >>= 1) t += __shfl_xor_sync(0xffffffffu, t, o);
        if (tid == 0) sm[0] = t;
    }
    __syncthreads();
    const float inv = 1.0f / sm[0];

    #pragma unroll
    for (int i = 0; i < 8; i++) p[tid + i * 256] = v[i] * inv;
}

// ---------------------------------------------------------------------------
// out = LayerNorm(x + y) * g + b, row length CD = 1024. One block per row.
// ---------------------------------------------------------------------------
__global__ void __launch_bounds__(256)
add_ln_k(const float* __restrict__ x, const float* __restrict__ y,
         const float* __restrict__ g, const float* __restrict__ b,
         float* __restrict__ out)
{
    const long long row = blockIdx.x;
    const float* px = x + row * (long long)CD;
    const float* py = y + row * (long long)CD;
    float* po = out + row * (long long)CD;
    const int tid = threadIdx.x;
    __shared__ float sm[16];

    float v[4];
    float s = 0.f, s2 = 0.f;
    #pragma unroll
    for (int i = 0; i < 4; i++) {
        float t = px[tid + i * 256] + py[tid + i * 256];
        v[i] = t; s += t; s2 += t * t;
    }
    #pragma unroll
    for (int o = 16; o; o >>= 1) {
        s  += __shfl_xor_sync(0xffffffffu, s,  o);
        s2 += __shfl_xor_sync(0xffffffffu, s2, o);
    }
    if ((tid & 31) == 0) { sm[tid >> 5] = s; sm[8 + (tid >> 5)] = s2; }
    __syncthreads();
    if (tid < 32) {
        float t  = (tid < 8) ? sm[tid]     : 0.f;
        float t2 = (tid < 8) ? sm[8 + tid] : 0.f;
        #pragma unroll
        for (int o = 4; o; o >>= 1) {
            t  += __shfl_xor_sync(0xffffffffu, t,  o);
            t2 += __shfl_xor_sync(0xffffffffu, t2, o);
        }
        if (tid == 0) { sm[0] = t; sm[8] = t2; }
    }
    __syncthreads();
    const float mean = sm[0] * (1.0f / CD);
    const float var  = sm[8] * (1.0f / CD) - mean * mean;
    const float rs = rsqrtf(var + 1e-5f);

    #pragma unroll
    for (int i = 0; i < 4; i++) {
        const int c = tid + i * 256;
        po[c] = (v[i] - mean) * rs * g[c] + b[c];
    }
}

// ---------------------------------------------------------------------------
// kernel_launch
// ---------------------------------------------------------------------------
extern "C" void kernel_launch(void* const* d_in, const int* in_sizes, int n_in,
                              void* d_out, int out_size)
{
    const float* x   = (const float*)d_in[0];
    const float* Wq  = (const float*)d_in[1];
    const float* Wk  = (const float*)d_in[2];
    const float* Wv  = (const float*)d_in[3];
    const float* Wo  = (const float*)d_in[4];
    const float* bo  = (const float*)d_in[5];
    const float* w1  = (const float*)d_in[6];
    const float* b1  = (const float*)d_in[7];
    const float* w2  = (const float*)d_in[8];
    const float* b2  = (const float*)d_in[9];
    const float* w3  = (const float*)d_in[10];
    const float* b3  = (const float*)d_in[11];
    const float* w4  = (const float*)d_in[12];
    const float* b4  = (const float*)d_in[13];
    const float* g1  = (const float*)d_in[14];
    const float* be1 = (const float*)d_in[15];
    const float* g2  = (const float*)d_in[16];
    const float* be2 = (const float*)d_in[17];
    float* out = (float*)d_out;

    float *Q, *Kp, *V, *SC, *ZC, *AO, *Z1, *Y1, *Y2;
    cudaGetSymbolAddress((void**)&Q,  g_Q);
    cudaGetSymbolAddress((void**)&Kp, g_K);
    cudaGetSymbolAddress((void**)&V,  g_V);
    cudaGetSymbolAddress((void**)&SC, g_SC);
    cudaGetSymbolAddress((void**)&ZC, g_ZC);
    cudaGetSymbolAddress((void**)&AO, g_AO);
    cudaGetSymbolAddress((void**)&Z1, g_Z1);
    cudaGetSymbolAddress((void**)&Y1, g_Y1);
    cudaGetSymbolAddress((void**)&Y2, g_Y2);

    const int MT = CB * CS;                 // 8192 tokens
    const long long HBD = (long long)CB * CS * CD;   // per-head Q/K/V stride
    const long long SD  = (long long)CS * CD;
    const long long SS  = (long long)CS * CS;

    // 1-3. QKV projections: X[8192,1024] x W[h][1024,1024] -> [h][8192,1024]
    {
        dim3 grid(CD / 128, MT / 128, CH);
        gemm_k<false, false, false><<<grid, 256>>>(x, Wq, Q, nullptr,
            MT, CD, CD, CD, CD, CD, 0, (long long)CD * CD, HBD, 0, 1, 1.0f);
        gemm_k<false, false, false><<<grid, 256>>>(x, Wk, Kp, nullptr,
            MT, CD, CD, CD, CD, CD, 0, (long long)CD * CD, HBD, 0, 1, 1.0f);
        gemm_k<false, false, false><<<grid, 256>>>(x, Wv, V, nullptr,
            MT, CD, CD, CD, CD, CD, 0, (long long)CD * CD, HBD, 0, 1, 1.0f);
    }

    // 4. scores = Q K^T * (1/32), per (h,b): [2048,1024] x [2048,1024]^T
    {
        dim3 grid(CS / 128, CS / 128, CH * CB);
        gemm_k<true, false, false><<<grid, 256>>>(Q, Kp, SC, nullptr,
            CS, CS, CD, CD, CD, CS, SD, SD, SS, 0, 1, 0.03125f);
    }

    // 5. softmax over rows (H*B*S rows of length S)
    softmax_k<<<CH * CB * CS, 256>>>(SC);

    // 6. Z = attn @ V, written in head-concat layout ZC[b][s][h*D+e]
    //    z index = h*CB + b ; C offset = (z/CB)*D + (z%CB)*(S*H*D), ldc = H*D
    {
        dim3 grid(CD / 128, CS / 128, CH * CB);
        gemm_k<false, false, false><<<grid, 256>>>(SC, V, ZC, nullptr,
            CS, CD, CS, CS, CD, CH * CD, SS, SD,
            (long long)CD, (long long)CS * CH * CD, CB, 1.0f);
    }

    // 7. attn_out = ZC[8192, 8192] @ Wo[8192,1024] + bo
    {
        dim3 grid(CD / 128, MT / 128, 1);
        gemm_k<false, false, true><<<grid, 256>>>(ZC, Wo, AO, bo,
            MT, CD, CH * CD, CH * CD, CD, CD, 0, 0, 0, 0, 1, 1.0f);
    }

    // 8. Z1 = LN(x + attn_out)
    add_ln_k<<<MT, 256>>>(x, AO, g1, be1, Z1);

    // 9-12. FFN
    {
        dim3 g1d(CHID / 128, MT / 128, 1);
        gemm_k<false, true, true><<<g1d, 256>>>(Z1, w1, Y1, b1,
            MT, CHID, CD, CD, CHID, CHID, 0, 0, 0, 0, 1, 1.0f);
        gemm_k<false, true, true><<<g1d, 256>>>(Y1, w2, Y2, b2,
            MT, CHID, CHID, CHID, CHID, CHID, 0, 0, 0, 0, 1, 1.0f);
        gemm_k<false, true, true><<<g1d, 256>>>(Y2, w3, Y1, b3,
            MT, CHID, CHID, CHID, CHID, CHID, 0, 0, 0, 0, 1, 1.0f);
        dim3 g4(CD / 128, MT / 128, 1);
        gemm_k<false, false, true><<<g4, 256>>>(Y1, w4, AO, b4,
            MT, CD, CHID, CHID, CD, CD, 0, 0, 0, 0, 1, 1.0f);
    }

    // 13. out = LN(Z1 + ffn_out)
    add_ln_k<<<MT, 256>>>(Z1, AO, g2, be2, out);
}

// round 7
// speedup vs baseline: 2.5135x; 2.5109x over previous
#include <cuda_runtime.h>
#include <cuda_bf16.h>
#include <math.h>

typedef unsigned int u32;
typedef unsigned long long u64;

#define CB 4
#define CS 2048
#define CD 1024
#define CH 8
#define CHID 4096

// ---------------- scratch (device globals) ----------------
// packed u32 = bf16(hi) | bf16(x-hi)<<16 ; all GEMM operands K-major.
__device__ u32 g_Xp [(size_t)CB*CS*CD];
__device__ u32 g_TWq[(size_t)CH*CD*CD];
__device__ u32 g_TWk[(size_t)CH*CD*CD];
__device__ u32 g_TWv[(size_t)CH*CD*CD];
__device__ u32 g_TWo[(size_t)CD*CH*CD];
__device__ u32 g_Tw1[(size_t)CHID*CD];
__device__ u32 g_Tw2[(size_t)CHID*CHID];
__device__ u32 g_Tw3[(size_t)CHID*CHID];
__device__ u32 g_Tw4[(size_t)CD*CHID];
__device__ u32 g_Qp [(size_t)CH*CB*CS*CD];   // [(h,b)][s][d]
__device__ u32 g_Kp2[(size_t)CH*CB*CS*CD];   // [(h,b)][t][d]
__device__ u32 g_VTp[(size_t)CH*CB*CD*CS];   // [h][b][e][t]
__device__ float g_SC[(size_t)CH*CB*CS*CS];
__device__ u32 g_ATp[(size_t)CH*CB*CS*CS];
__device__ u32 g_ZCp[(size_t)CB*CS*CH*CD];   // [token][h*D+e]
__device__ u32 g_Y1p[(size_t)CB*CS*CHID];
__device__ u32 g_Y2p[(size_t)CB*CS*CHID];
__device__ float g_AO[(size_t)CB*CS*CD];
__device__ float g_Z1[(size_t)CB*CS*CD];
__device__ u32 g_Z1p[(size_t)CB*CS*CD];

// ---------------- helpers ----------------
__device__ __forceinline__ u32 smem_u32(const void* p){
    u32 a; asm("{ .reg .u64 t; cvta.to.shared.u64 t, %1; cvt.u32.u64 %0, t; }":"=r"(a):"l"(p)); return a;
}
__device__ __forceinline__ u32 pack_hl(float v){
    __nv_bfloat16 h = __float2bfloat16(v);
    float hf = __bfloat162float(h);
    __nv_bfloat16 l = __float2bfloat16(v - hf);
    return (u32)__bfloat16_as_ushort(h) | ((u32)__bfloat16_as_ushort(l) << 16);
}

#define LDM_X4(r, a) asm volatile( \
    "ldmatrix.sync.aligned.m8n8.x4.shared.b16 {%0,%1,%2,%3}, [%4];" \
    : "=r"((r)[0]),"=r"((r)[1]),"=r"((r)[2]),"=r"((r)[3]) : "r"(a))

#define MMA_BF16(c, a, b0v, b1v) asm volatile( \
    "mma.sync.aligned.m16n8k16.row.col.f32.bf16.bf16.f32 " \
    "{%0,%1,%2,%3},{%4,%5,%6,%7},{%8,%9},{%0,%1,%2,%3};" \
    : "+f"((c)[0]),"+f"((c)[1]),"+f"((c)[2]),"+f"((c)[3]) \
    : "r"((a)[0]),"r"((a)[1]),"r"((a)[2]),"r"((a)[3]), "r"(b0v),"r"(b1v))

// ---------------- mma.sync GEMM: 128x128 tile, K-chunk 32, bf16x3 ----------------
// D[m][n] = alpha * sum_k A[m][k]*B[n][k] (+bias) (+relu), operands packed u32.
// MODE: 0 fp32 out, 1 packed out, 2 packed transposed-per-batch out (V proj).
// C offset = (z/cdiv)*cs1 + (z%cdiv)*cs2.
template<int MODE, bool BIAS, bool RELU>
__global__ void __launch_bounds__(256, 1)
tgemm(const u32* __restrict__ Ag, const u32* __restrict__ Bg,
      void* __restrict__ Cg, const float* __restrict__ bias,
      int K, int lda, int ldb, int ldc,
      long long sA, long long sB, long long cs1, long long cs2, int cdiv,
      float alpha)
{
    __shared__ __align__(16) char sAhi[8192], sAlo[8192], sBhi[8192], sBlo[8192];

    const int tid = threadIdx.x, lane = tid & 31, wid = tid >> 5;
    const int wm = wid >> 2, wn = wid & 3;              // 2 x 4 warp grid
    const int z = blockIdx.z, m0 = blockIdx.y * 128, n0 = blockIdx.x * 128;

    Ag += (long long)z * sA + (long long)m0 * lda;
    Bg += (long long)z * sB + (long long)n0 * ldb;
    const long long coff = (long long)(z / cdiv) * cs1 + (long long)(z % cdiv) * cs2;

    float acc[4][4][4];
    #pragma unroll
    for (int i = 0; i < 4; i++)
        #pragma unroll
        for (int j = 0; j < 4; j++)
            #pragma unroll
            for (int q = 0; q < 4; q++) acc[i][j][q] = 0.f;

    // loader decode: idx = j*256+tid -> row = j*32 + (tid>>3), 4-elt group g = tid&7
    const int lrow = tid >> 3, lg = tid & 7;
    // swizzled 8B store slot (j*32 doesn't change (row>>1)&3)
    const u32 sbase = (u32)lrow * 64 + ((u32)((lg >> 1) ^ ((lrow >> 1) & 3)) << 4) + (u32)(lg & 1) * 8;

    const u32 ah_b = smem_u32(sAhi), al_b = smem_u32(sAlo);
    const u32 bh_b = smem_u32(sBhi), bl_b = smem_u32(sBlo);

    const int NT = K >> 5;
    uint4 buf[8];
    #pragma unroll
    for (int j = 0; j < 4; j++) {
        buf[j]     = *(const uint4*)(Ag + (long long)(j * 32 + lrow) * lda + lg * 4);
        buf[4 + j] = *(const uint4*)(Bg + (long long)(j * 32 + lrow) * ldb + lg * 4);
    }

    for (int c = 0; c < NT; c++) {
        if (c) __syncthreads();
        #pragma unroll
        for (int j = 0; j < 4; j++) {
            const uint4 va = buf[j], vb = buf[4 + j];
            const u32 off = (u32)j * 2048 + sbase;
            *(uint2*)(sAhi + off) = make_uint2(__byte_perm(va.x, va.y, 0x5410), __byte_perm(va.z, va.w, 0x5410));
            *(uint2*)(sAlo + off) = make_uint2(__byte_perm(va.x, va.y, 0x7632), __byte_perm(va.z, va.w, 0x7632));
            *(uint2*)(sBhi + off) = make_uint2(__byte_perm(vb.x, vb.y, 0x5410), __byte_perm(vb.z, vb.w, 0x5410));
            *(uint2*)(sBlo + off) = make_uint2(__byte_perm(vb.x, vb.y, 0x7632), __byte_perm(vb.z, vb.w, 0x7632));
        }
        __syncthreads();
        if (c + 1 < NT) {
            const int kb = (c + 1) * 32;
            #pragma unroll
            for (int j = 0; j < 4; j++) {
                buf[j]     = *(const uint4*)(Ag + (long long)(j * 32 + lrow) * lda + kb + lg * 4);
                buf[4 + j] = *(const uint4*)(Bg + (long long)(j * 32 + lrow) * ldb + kb + lg * 4);
            }
        }
        #pragma unroll
        for (int kk = 0; kk < 2; kk++) {
            u32 ah[4][4], al[4][4], bh[4][2], bl[4][2];
            // A fragments: rows m, lanes 0-15 -> k seg kk*2, 16-31 -> kk*2+1
            const int arow = wm * 64 + (lane & 15);
            const int aks  = kk * 2 + (lane >> 4);
            #pragma unroll
            for (int mt = 0; mt < 4; mt++) {
                const int ro = arow + mt * 16;
                const u32 off = (u32)ro * 64 + ((u32)(aks ^ ((ro >> 1) & 3)) << 4);
                LDM_X4(ah[mt], ah_b + off);
                LDM_X4(al[mt], al_b + off);
            }
            // B fragments: x4 covers two n8 tiles
            const int brow0 = wn * 32 + ((lane >> 4) & 1) * 8 + (lane & 7);
            const int bks = kk * 2 + ((lane >> 3) & 1);
            #pragma unroll
            for (int np = 0; np < 2; np++) {
                const int ro = brow0 + np * 16;
                const u32 off = (u32)ro * 64 + ((u32)(bks ^ ((ro >> 1) & 3)) << 4);
                u32 t[4];
                LDM_X4(t, bh_b + off);
                bh[np*2][0] = t[0]; bh[np*2][1] = t[1]; bh[np*2+1][0] = t[2]; bh[np*2+1][1] = t[3];
                LDM_X4(t, bl_b + off);
                bl[np*2][0] = t[0]; bl[np*2][1] = t[1]; bl[np*2+1][0] = t[2]; bl[np*2+1][1] = t[3];
            }
            #pragma unroll
            for (int mt = 0; mt < 4; mt++)
                #pragma unroll
                for (int nt = 0; nt < 4; nt++)
                    MMA_BF16(acc[mt][nt], ah[mt], bh[nt][0], bh[nt][1]);
            #pragma unroll
            for (int mt = 0; mt < 4; mt++)
                #pragma unroll
                for (int nt = 0; nt < 4; nt++)
                    MMA_BF16(acc[mt][nt], ah[mt], bl[nt][0], bl[nt][1]);
            #pragma unroll
            for (int mt = 0; mt < 4; mt++)
                #pragma unroll
                for (int nt = 0; nt < 4; nt++)
                    MMA_BF16(acc[mt][nt], al[mt], bh[nt][0], bh[nt][1]);
        }
    }

    // ---- epilogue: D frag thread map: rows lane>>2 (+8), cols (lane&3)*2 ----
    const int er = lane >> 2, ec = (lane & 3) * 2;
    #pragma unroll
    for (int mt = 0; mt < 4; mt++) {
        #pragma unroll
        for (int nt = 0; nt < 4; nt++) {
            const float* a4 = acc[mt][nt];
            const int row0 = m0 + wm * 64 + mt * 16 + er;
            const int col  = n0 + wn * 32 + nt * 8 + ec;
            float v00 = a4[0] * alpha, v01 = a4[1] * alpha;
            float v10 = a4[2] * alpha, v11 = a4[3] * alpha;
            if (BIAS) {
                const float bb0 = bias[col], bb1 = bias[col + 1];
                v00 += bb0; v01 += bb1; v10 += bb0; v11 += bb1;
            }
            if (RELU) {
                v00 = fmaxf(v00, 0.f); v01 = fmaxf(v01, 0.f);
                v10 = fmaxf(v10, 0.f); v11 = fmaxf(v11, 0.f);
            }
            if (MODE == 0) {
                float* C = (float*)Cg + coff;
                *(float2*)(C + (long long)row0 * ldc + col)       = make_float2(v00, v01);
                *(float2*)(C + (long long)(row0 + 8) * ldc + col) = make_float2(v10, v11);
            } else if (MODE == 1) {
                u32* C = (u32*)Cg + coff;
                *(uint2*)(C + (long long)row0 * ldc + col)       = make_uint2(pack_hl(v00), pack_hl(v01));
                *(uint2*)(C + (long long)(row0 + 8) * ldc + col) = make_uint2(pack_hl(v10), pack_hl(v11));
            } else {
                // transposed: addr(e, token) = coff + (tok>>11)*(CD*CS) + (tok&2047) + e*CS
                u32* C = (u32*)Cg;
                const long long o0 = coff + (long long)(row0 >> 11) * ((long long)CD * CS) + (row0 & (CS - 1));
                const int r1 = row0 + 8;
                const long long o1 = coff + (long long)(r1 >> 11) * ((long long)CD * CS) + (r1 & (CS - 1));
                C[o0 + (long long)col * CS]       = pack_hl(v00);
                C[o0 + (long long)(col + 1) * CS] = pack_hl(v01);
                C[o1 + (long long)col * CS]       = pack_hl(v10);
                C[o1 + (long long)(col + 1) * CS] = pack_hl(v11);
            }
        }
    }
}

// ---------------- fp32 -> packed ----------------
__global__ void __launch_bounds__(256)
conv_pack_k(const float* __restrict__ in, u32* __restrict__ out){
    const long long i = (long long)blockIdx.x * 256 + threadIdx.x;
    out[i] = pack_hl(in[i]);
}

// ---------------- fp32 [R,C] -> packed [C,R] (batched) ----------------
__global__ void __launch_bounds__(256)
transp_pack_k(const float* __restrict__ in, u32* __restrict__ out,
              int R, int Cc, long long sIn, long long sOut){
    __shared__ float sm[32][33];
    const float* ip = in + (long long)blockIdx.z * sIn;
    u32* op = out + (long long)blockIdx.z * sOut;
    const int x0 = blockIdx.x * 32, y0 = blockIdx.y * 32;
    const int tx = threadIdx.x & 31, ty = threadIdx.x >> 5;
    #pragma unroll
    for (int j = 0; j < 32; j += 8)
        sm[ty + j][tx] = ip[(long long)(y0 + ty + j) * Cc + x0 + tx];
    __syncthreads();
    #pragma unroll
    for (int j = 0; j < 32; j += 8)
        op[(long long)(x0 + ty + j) * R + y0 + tx] = pack_hl(sm[tx][ty + j]);
}

// ---------------- softmax row 2048, fp32 in -> packed out ----------------
__global__ void __launch_bounds__(256)
softmax_pack_k(const float* __restrict__ sc, u32* __restrict__ outp){
    const long long row = blockIdx.x;
    const float* p = sc + row * (long long)CS;
    u32* o = outp + row * (long long)CS;
    const int tid = threadIdx.x;
    __shared__ float sm[8];
    float v[8], mx = -3.4e38f;
    #pragma unroll
    for (int i = 0; i < 8; i++){ v[i] = p[tid + i*256]; mx = fmaxf(mx, v[i]); }
    #pragma unroll
    for (int w = 16; w; w >>= 1) mx = fmaxf(mx, __shfl_xor_sync(~0u, mx, w));
    if ((tid & 31) == 0) sm[tid >> 5] = mx;
    __syncthreads();
    if (tid < 32){
        float t = (tid < 8) ? sm[tid] : -3.4e38f;
        #pragma unroll
        for (int w = 4; w; w >>= 1) t = fmaxf(t, __shfl_xor_sync(~0u, t, w));
        if (tid == 0) sm[0] = t;
    }
    __syncthreads(); mx = sm[0]; __syncthreads();
    float s = 0.f;
    #pragma unroll
    for (int i = 0; i < 8; i++){ v[i] = __expf(v[i] - mx); s += v[i]; }
    #pragma unroll
    for (int w = 16; w; w >>= 1) s += __shfl_xor_sync(~0u, s, w);
    if ((tid & 31) == 0) sm[tid >> 5] = s;
    __syncthreads();
    if (tid < 32){
        float t = (tid < 8) ? sm[tid] : 0.f;
        #pragma unroll
        for (int w = 4; w; w >>= 1) t += __shfl_xor_sync(~0u, t, w);
        if (tid == 0) sm[0] = t;
    }
    __syncthreads();
    const float inv = 1.0f / sm[0];
    #pragma unroll
    for (int i = 0; i < 8; i++) o[tid + i*256] = pack_hl(v[i] * inv);
}

// ---------------- out = LN(x+y)*g+b (+packed copy) ----------------
template<bool PK>
__global__ void __launch_bounds__(256)
add_ln_k(const float* __restrict__ x, const float* __restrict__ y,
         const float* __restrict__ g, const float* __restrict__ b,
         float* __restrict__ out, u32* __restrict__ outp){
    const long long row = blockIdx.x;
    const float* px = x + row * (long long)CD;
    const float* py = y + row * (long long)CD;
    float* po = out + row * (long long)CD;
    const int tid = threadIdx.x;
    __shared__ float sm[16];
    float v[4], s = 0.f, s2 = 0.f;
    #pragma unroll
    for (int i = 0; i < 4; i++){
        float t = px[tid + i*256] + py[tid + i*256];
        v[i] = t; s += t; s2 += t*t;
    }
    #pragma unroll
    for (int w = 16; w; w >>= 1){ s += __shfl_xor_sync(~0u, s, w); s2 += __shfl_xor_sync(~0u, s2, w); }
    if ((tid & 31) == 0){ sm[tid>>5] = s; sm[8 + (tid>>5)] = s2; }
    __syncthreads();
    if (tid < 32){
        float t = (tid < 8) ? sm[tid] : 0.f, t2 = (tid < 8) ? sm[8+tid] : 0.f;
        #pragma unroll
        for (int w = 4; w; w >>= 1){ t += __shfl_xor_sync(~0u, t, w); t2 += __shfl_xor_sync(~0u, t2, w); }
        if (tid == 0){ sm[0] = t; sm[8] = t2; }
    }
    __syncthreads();
    const float mean = sm[0] * (1.0f/CD);
    const float var  = sm[8] * (1.0f/CD) - mean*mean;
    const float rs = rsqrtf(var + 1e-5f);
    #pragma unroll
    for (int i = 0; i < 4; i++){
        const int c = tid + i*256;
        const float o = (v[i] - mean) * rs * g[c] + b[c];
        po[c] = o;
        if (PK) outp[row * (long long)CD + c] = pack_hl(o);
    }
}

// ---------------- kernel_launch ----------------
extern "C" void kernel_launch(void* const* d_in, const int* in_sizes, int n_in,
                              void* d_out, int out_size)
{
    const float* x  = (const float*)d_in[0];
    const float* Wq = (const float*)d_in[1];
    const float* Wk = (const float*)d_in[2];
    const float* Wv = (const float*)d_in[3];
    const float* Wo = (const float*)d_in[4];
    const float* bo = (const float*)d_in[5];
    const float* w1 = (const float*)d_in[6];
    const float* b1 = (const float*)d_in[7];
    const float* w2 = (const float*)d_in[8];
    const float* b2 = (const float*)d_in[9];
    const float* w3 = (const float*)d_in[10];
    const float* b3 = (const float*)d_in[11];
    const float* w4 = (const float*)d_in[12];
    const float* b4 = (const float*)d_in[13];
    const float* g1 = (const float*)d_in[14];
    const float* be1= (const float*)d_in[15];
    const float* g2 = (const float*)d_in[16];
    const float* be2= (const float*)d_in[17];
    float* out = (float*)d_out;

    u32 *Xp,*TWq,*TWk,*TWv,*TWo,*Tw1,*Tw2,*Tw3,*Tw4,*Qp,*Kp,*VTp,*ATp,*ZCp,*Y1p,*Y2p,*Z1p;
    float *SC,*AO,*Z1;
    cudaGetSymbolAddress((void**)&Xp, g_Xp);   cudaGetSymbolAddress((void**)&TWq, g_TWq);
    cudaGetSymbolAddress((void**)&TWk, g_TWk); cudaGetSymbolAddress((void**)&TWv, g_TWv);
    cudaGetSymbolAddress((void**)&TWo, g_TWo); cudaGetSymbolAddress((void**)&Tw1, g_Tw1);
    cudaGetSymbolAddress((void**)&Tw2, g_Tw2); cudaGetSymbolAddress((void**)&Tw3, g_Tw3);
    cudaGetSymbolAddress((void**)&Tw4, g_Tw4); cudaGetSymbolAddress((void**)&Qp, g_Qp);
    cudaGetSymbolAddress((void**)&Kp, g_Kp2);  cudaGetSymbolAddress((void**)&VTp, g_VTp);
    cudaGetSymbolAddress((void**)&SC, g_SC);   cudaGetSymbolAddress((void**)&ATp, g_ATp);
    cudaGetSymbolAddress((void**)&ZCp, g_ZCp); cudaGetSymbolAddress((void**)&Y1p, g_Y1p);
    cudaGetSymbolAddress((void**)&Y2p, g_Y2p); cudaGetSymbolAddress((void**)&AO, g_AO);
    cudaGetSymbolAddress((void**)&Z1, g_Z1);   cudaGetSymbolAddress((void**)&Z1p, g_Z1p);

    const int MT = CB * CS;                       // 8192
    const long long DD  = (long long)CD * CD;
    const long long HBD = (long long)CB * CS * CD;
    const long long SD  = (long long)CS * CD;
    const long long SS  = (long long)CS * CS;

    // ---- prep: pack x, transpose+pack weights ----
    conv_pack_k<<<MT * CD / 256, 256>>>(x, Xp);
    transp_pack_k<<<dim3(32, 32, CH), 256>>>(Wq, TWq, CD, CD, DD, DD);
    transp_pack_k<<<dim3(32, 32, CH), 256>>>(Wk, TWk, CD, CD, DD, DD);
    transp_pack_k<<<dim3(32, 32, CH), 256>>>(Wv, TWv, CD, CD, DD, DD);
    transp_pack_k<<<dim3(32, 256, 1), 256>>>(Wo, TWo, CH * CD, CD, 0, 0);
    transp_pack_k<<<dim3(128, 32, 1), 256>>>(w1, Tw1, CD, CHID, 0, 0);
    transp_pack_k<<<dim3(128, 128, 1), 256>>>(w2, Tw2, CHID, CHID, 0, 0);
    transp_pack_k<<<dim3(128, 128, 1), 256>>>(w3, Tw3, CHID, CHID, 0, 0);
    transp_pack_k<<<dim3(32, 128, 1), 256>>>(w4, Tw4, CHID, CD, 0, 0);

    // ---- QKV: Xp[8192,1024] x TW[h][1024,1024] ----
    {
        dim3 grid(CD / 128, MT / 128, CH);
        tgemm<1,false,false><<<grid, 256>>>(Xp, TWq, Qp, nullptr,
            CD, CD, CD, CD, 0, DD, HBD, 0, 1, 1.0f);
        tgemm<1,false,false><<<grid, 256>>>(Xp, TWk, Kp, nullptr,
            CD, CD, CD, CD, 0, DD, HBD, 0, 1, 1.0f);
        tgemm<2,false,false><<<grid, 256>>>(Xp, TWv, VTp, nullptr,
            CD, CD, CD, 0, 0, DD, HBD, 0, 1, 1.0f);
    }
    // ---- scores = Q K^T / 32, per (h,b) ----
    {
        dim3 grid(CS / 128, CS / 128, CH * CB);
        tgemm<0,false,false><<<grid, 256>>>(Qp, Kp, SC, nullptr,
            CD, CD, CD, CS, SD, SD, SS, 0, 1, 0.03125f);
    }
    // ---- softmax + pack ----
    softmax_pack_k<<<CH * CB * CS, 256>>>(SC, ATp);
    // ---- Z = attn @ V -> head-concat packed ----
    {
        dim3 grid(CD / 128, CS / 128, CH * CB);
        tgemm<1,false,false><<<grid, 256>>>(ATp, VTp, ZCp, nullptr,
            CS, CS, CS, CH * CD, SS, (long long)CD * CS,
            (long long)CD, (long long)CS * CH * CD, CB, 1.0f);
    }
    // ---- attn_out = ZC @ Wo + bo ----
    {
        dim3 grid(CD / 128, MT / 128, 1);
        tgemm<0,true,false><<<grid, 256>>>(ZCp, TWo, AO, bo,
            CH * CD, CH * CD, CH * CD, CD, 0, 0, 0, 0, 1, 1.0f);
    }
    // ---- Z1 = LN(x + attn_out) ----
    add_ln_k<true><<<MT, 256>>>(x, AO, g1, be1, Z1, Z1p);
    // ---- FFN ----
    {
        dim3 gh(CHID / 128, MT / 128, 1);
        tgemm<1,true,true><<<gh, 256>>>(Z1p, Tw1, Y1p, b1,
            CD, CD, CD, CHID, 0, 0, 0, 0, 1, 1.0f);
        tgemm<1,true,true><<<gh, 256>>>(Y1p, Tw2, Y2p, b2,
            CHID, CHID, CHID, CHID, 0, 0, 0, 0, 1, 1.0f);
        tgemm<1,true,true><<<gh, 256>>>(Y2p, Tw3, Y1p, b3,
            CHID, CHID, CHID, CHID, 0, 0, 0, 0, 1, 1.0f);
        dim3 g4(CD / 128, MT / 128, 1);
        tgemm<0,true,false><<<g4, 256>>>(Y1p, Tw4, AO, b4,
            CHID, CHID, CHID, CD, 0, 0, 0, 0, 1, 1.0f);
    }
    // ---- out = LN(Z1 + ffn_out) ----
    add_ln_k<false><<<MT, 256>>>(Z1, AO, g2, be2, out, nullptr);
}

// round 9
// speedup vs baseline: 2.7696x; 1.1019x over previous
#include <cuda_runtime.h>
#include <cuda_bf16.h>
#include <math.h>

typedef unsigned int u32;
typedef unsigned long long u64;

#define CB 4
#define CS 2048
#define CD 1024
#define CH 8
#define CHID 4096

// ---------------- scratch (device globals) ----------------
// packed u32 = bf16(hi) | bf16(x-hi)<<16 ; all GEMM operands K-major.
__device__ u32 g_Xp [(size_t)CB*CS*CD];
__device__ u32 g_TWq[(size_t)CH*CD*CD];
__device__ u32 g_TWk[(size_t)CH*CD*CD];
__device__ u32 g_TWv[(size_t)CH*CD*CD];
__device__ u32 g_TWo[(size_t)CD*CH*CD];
__device__ u32 g_Tw1[(size_t)CHID*CD];
__device__ u32 g_Tw2[(size_t)CHID*CHID];
__device__ u32 g_Tw3[(size_t)CHID*CHID];
__device__ u32 g_Tw4[(size_t)CD*CHID];
__device__ u32 g_Qp [(size_t)CH*CB*CS*CD];   // [(h,b)][s][d]
__device__ u32 g_Kp2[(size_t)CH*CB*CS*CD];   // [(h,b)][t][d]
__device__ u32 g_VTp[(size_t)CH*CB*CD*CS];   // [h][b][e][t]
__device__ float g_SC[(size_t)CH*CB*CS*CS];
__device__ u32 g_ATp[(size_t)CH*CB*CS*CS];
__device__ u32 g_ZCp[(size_t)CB*CS*CH*CD];   // [token][h*D+e]
__device__ u32 g_Y1p[(size_t)CB*CS*CHID];
__device__ u32 g_Y2p[(size_t)CB*CS*CHID];
__device__ float g_AO[(size_t)CB*CS*CD];
__device__ float g_Z1[(size_t)CB*CS*CD];
__device__ u32 g_Z1p[(size_t)CB*CS*CD];

// ---------------- helpers ----------------
__device__ __forceinline__ u32 smem_u32(const void* p){
    u32 a; asm("{ .reg .u64 t; cvta.to.shared.u64 t, %1; cvt.u32.u64 %0, t; }":"=r"(a):"l"(p)); return a;
}
__device__ __forceinline__ u32 pack_hl(float v){
    __nv_bfloat16 h = __float2bfloat16(v);
    float hf = __bfloat162float(h);
    __nv_bfloat16 l = __float2bfloat16(v - hf);
    return (u32)__bfloat16_as_ushort(h) | ((u32)__bfloat16_as_ushort(l) << 16);
}

#define LDM_X4(r, a) asm volatile( \
    "ldmatrix.sync.aligned.m8n8.x4.shared.b16 {%0,%1,%2,%3}, [%4];" \
    : "=r"((r)[0]),"=r"((r)[1]),"=r"((r)[2]),"=r"((r)[3]) : "r"(a))

#define MMA_BF16(c, a, b0v, b1v) asm volatile( \
    "mma.sync.aligned.m16n8k16.row.col.f32.bf16.bf16.f32 " \
    "{%0,%1,%2,%3},{%4,%5,%6,%7},{%8,%9},{%0,%1,%2,%3};" \
    : "+f"((c)[0]),"+f"((c)[1]),"+f"((c)[2]),"+f"((c)[3]) \
    : "r"((a)[0]),"r"((a)[1]),"r"((a)[2]),"r"((a)[3]), "r"(b0v),"r"(b1v))

// ---------------- mma.sync GEMM: 128x128 tile, K-chunk 32, bf16x3 ----------------
// Double-buffered SMEM (2 x 32KB stages), ONE __syncthreads per K-chunk.
// D[m][n] = alpha * sum_k A[m][k]*B[n][k] (+bias) (+relu), operands packed u32.
// MODE: 0 fp32 out, 1 packed out, 2 packed transposed-per-batch out (V proj).
#define STG_SZ   32768
#define PL_AHI   0
#define PL_ALO   8192
#define PL_BHI   16384
#define PL_BLO   24576
#define TG_SMEM  (2 * STG_SZ)

template<int MODE, bool BIAS, bool RELU>
__global__ void __launch_bounds__(256, 1)
tgemm(const u32* __restrict__ Ag, const u32* __restrict__ Bg,
      void* __restrict__ Cg, const float* __restrict__ bias,
      int K, int lda, int ldb, int ldc,
      long long sA, long long sB, long long cs1, long long cs2, int cdiv,
      float alpha)
{
    extern __shared__ __align__(16) char smem[];

    const int tid = threadIdx.x, lane = tid & 31, wid = tid >> 5;
    const int wm = wid >> 2, wn = wid & 3;              // 2 x 4 warp grid
    const int z = blockIdx.z, m0 = blockIdx.y * 128, n0 = blockIdx.x * 128;

    Ag += (long long)z * sA + (long long)m0 * lda;
    Bg += (long long)z * sB + (long long)n0 * ldb;
    const long long coff = (long long)(z / cdiv) * cs1 + (long long)(z % cdiv) * cs2;

    float acc[4][4][4];
    #pragma unroll
    for (int i = 0; i < 4; i++)
        #pragma unroll
        for (int j = 0; j < 4; j++)
            #pragma unroll
            for (int q = 0; q < 4; q++) acc[i][j][q] = 0.f;

    // loader decode: idx = j*256+tid -> row = j*32 + (tid>>3), 4-elt group g = tid&7
    const int lrow = tid >> 3, lg = tid & 7;
    const u32 sbase = (u32)lrow * 64 + ((u32)((lg >> 1) ^ ((lrow >> 1) & 3)) << 4) + (u32)(lg & 1) * 8;
    const u32 smb = smem_u32(smem);

    const int NT = K >> 5;
    uint4 buf[8];

    // prologue: chunk 0 -> stage 0; prefetch chunk 1 into regs
    #pragma unroll
    for (int j = 0; j < 4; j++) {
        buf[j]     = *(const uint4*)(Ag + (long long)(j * 32 + lrow) * lda + lg * 4);
        buf[4 + j] = *(const uint4*)(Bg + (long long)(j * 32 + lrow) * ldb + lg * 4);
    }
    #pragma unroll
    for (int j = 0; j < 4; j++) {
        const uint4 va = buf[j], vb = buf[4 + j];
        const u32 off = (u32)j * 2048 + sbase;
        *(uint2*)(smem + PL_AHI + off) = make_uint2(__byte_perm(va.x, va.y, 0x5410), __byte_perm(va.z, va.w, 0x5410));
        *(uint2*)(smem + PL_ALO + off) = make_uint2(__byte_perm(va.x, va.y, 0x7632), __byte_perm(va.z, va.w, 0x7632));
        *(uint2*)(smem + PL_BHI + off) = make_uint2(__byte_perm(vb.x, vb.y, 0x5410), __byte_perm(vb.z, vb.w, 0x5410));
        *(uint2*)(smem + PL_BLO + off) = make_uint2(__byte_perm(vb.x, vb.y, 0x7632), __byte_perm(vb.z, vb.w, 0x7632));
    }
    if (NT > 1) {
        #pragma unroll
        for (int j = 0; j < 4; j++) {
            buf[j]     = *(const uint4*)(Ag + (long long)(j * 32 + lrow) * lda + 32 + lg * 4);
            buf[4 + j] = *(const uint4*)(Bg + (long long)(j * 32 + lrow) * ldb + 32 + lg * 4);
        }
    }
    __syncthreads();

    for (int c = 0; c < NT; c++) {
        const int s = c & 1;
        const u32 stg = smb + (u32)s * STG_SZ;

        // ---- MMA on stage s ----
        #pragma unroll
        for (int kk = 0; kk < 2; kk++) {
            u32 ah[4][4], al[4][4], bh[4][2], bl[4][2];
            const int arow = wm * 64 + (lane & 15);
            const int aks  = kk * 2 + (lane >> 4);
            #pragma unroll
            for (int mt = 0; mt < 4; mt++) {
                const int ro = arow + mt * 16;
                const u32 off = (u32)ro * 64 + ((u32)(aks ^ ((ro >> 1) & 3)) << 4);
                LDM_X4(ah[mt], stg + PL_AHI + off);
                LDM_X4(al[mt], stg + PL_ALO + off);
            }
            const int brow0 = wn * 32 + ((lane >> 4) & 1) * 8 + (lane & 7);
            const int bks = kk * 2 + ((lane >> 3) & 1);
            #pragma unroll
            for (int np = 0; np < 2; np++) {
                const int ro = brow0 + np * 16;
                const u32 off = (u32)ro * 64 + ((u32)(bks ^ ((ro >> 1) & 3)) << 4);
                u32 t[4];
                LDM_X4(t, stg + PL_BHI + off);
                bh[np*2][0] = t[0]; bh[np*2][1] = t[1]; bh[np*2+1][0] = t[2]; bh[np*2+1][1] = t[3];
                LDM_X4(t, stg + PL_BLO + off);
                bl[np*2][0] = t[0]; bl[np*2][1] = t[1]; bl[np*2+1][0] = t[2]; bl[np*2+1][1] = t[3];
            }
            #pragma unroll
            for (int mt = 0; mt < 4; mt++)
                #pragma unroll
                for (int nt = 0; nt < 4; nt++)
                    MMA_BF16(acc[mt][nt], ah[mt], bh[nt][0], bh[nt][1]);
            #pragma unroll
            for (int mt = 0; mt < 4; mt++)
                #pragma unroll
                for (int nt = 0; nt < 4; nt++)
                    MMA_BF16(acc[mt][nt], ah[mt], bl[nt][0], bl[nt][1]);
            #pragma unroll
            for (int mt = 0; mt < 4; mt++)
                #pragma unroll
                for (int nt = 0; nt < 4; nt++)
                    MMA_BF16(acc[mt][nt], al[mt], bh[nt][0], bh[nt][1]);
        }

        // ---- store chunk c+1 into stage s^1, prefetch chunk c+2 ----
        if (c + 1 < NT) {
            char* st = smem + (s ^ 1) * STG_SZ;
            #pragma unroll
            for (int j = 0; j < 4; j++) {
                const uint4 va = buf[j], vb = buf[4 + j];
                const u32 off = (u32)j * 2048 + sbase;
                *(uint2*)(st + PL_AHI + off) = make_uint2(__byte_perm(va.x, va.y, 0x5410), __byte_perm(va.z, va.w, 0x5410));
                *(uint2*)(st + PL_ALO + off) = make_uint2(__byte_perm(va.x, va.y, 0x7632), __byte_perm(va.z, va.w, 0x7632));
                *(uint2*)(st + PL_BHI + off) = make_uint2(__byte_perm(vb.x, vb.y, 0x5410), __byte_perm(vb.z, vb.w, 0x5410));
                *(uint2*)(st + PL_BLO + off) = make_uint2(__byte_perm(vb.x, vb.y, 0x7632), __byte_perm(vb.z, vb.w, 0x7632));
            }
            if (c + 2 < NT) {
                const int kb = (c + 2) * 32;
                #pragma unroll
                for (int j = 0; j < 4; j++) {
                    buf[j]     = *(const uint4*)(Ag + (long long)(j * 32 + lrow) * lda + kb + lg * 4);
                    buf[4 + j] = *(const uint4*)(Bg + (long long)(j * 32 + lrow) * ldb + kb + lg * 4);
                }
            }
        }
        __syncthreads();
    }

    // ---- epilogue: D frag thread map: rows lane>>2 (+8), cols (lane&3)*2 ----
    const int er = lane >> 2, ec = (lane & 3) * 2;
    #pragma unroll
    for (int mt = 0; mt < 4; mt++) {
        #pragma unroll
        for (int nt = 0; nt < 4; nt++) {
            const float* a4 = acc[mt][nt];
            const int row0 = m0 + wm * 64 + mt * 16 + er;
            const int col  = n0 + wn * 32 + nt * 8 + ec;
            float v00 = a4[0] * alpha, v01 = a4[1] * alpha;
            float v10 = a4[2] * alpha, v11 = a4[3] * alpha;
            if (BIAS) {
                const float bb0 = bias[col], bb1 = bias[col + 1];
                v00 += bb0; v01 += bb1; v10 += bb0; v11 += bb1;
            }
            if (RELU) {
                v00 = fmaxf(v00, 0.f); v01 = fmaxf(v01, 0.f);
                v10 = fmaxf(v10, 0.f); v11 = fmaxf(v11, 0.f);
            }
            if (MODE == 0) {
                float* C = (float*)Cg + coff;
                *(float2*)(C + (long long)row0 * ldc + col)       = make_float2(v00, v01);
                *(float2*)(C + (long long)(row0 + 8) * ldc + col) = make_float2(v10, v11);
            } else if (MODE == 1) {
                u32* C = (u32*)Cg + coff;
                *(uint2*)(C + (long long)row0 * ldc + col)       = make_uint2(pack_hl(v00), pack_hl(v01));
                *(uint2*)(C + (long long)(row0 + 8) * ldc + col) = make_uint2(pack_hl(v10), pack_hl(v11));
            } else {
                u32* C = (u32*)Cg;
                const long long o0 = coff + (long long)(row0 >> 11) * ((long long)CD * CS) + (row0 & (CS - 1));
                const int r1 = row0 + 8;
                const long long o1 = coff + (long long)(r1 >> 11) * ((long long)CD * CS) + (r1 & (CS - 1));
                C[o0 + (long long)col * CS]       = pack_hl(v00);
                C[o0 + (long long)(col + 1) * CS] = pack_hl(v01);
                C[o1 + (long long)col * CS]       = pack_hl(v10);
                C[o1 + (long long)(col + 1) * CS] = pack_hl(v11);
            }
        }
    }
}

// ---------------- fp32 -> packed ----------------
__global__ void __launch_bounds__(256)
conv_pack_k(const float* __restrict__ in, u32* __restrict__ out){
    const long long i = (long long)blockIdx.x * 256 + threadIdx.x;
    out[i] = pack_hl(in[i]);
}

// ---------------- fp32 [R,C] -> packed [C,R] (batched) ----------------
__global__ void __launch_bounds__(256)
transp_pack_k(const float* __restrict__ in, u32* __restrict__ out,
              int R, int Cc, long long sIn, long long sOut){
    __shared__ float sm[32][33];
    const float* ip = in + (long long)blockIdx.z * sIn;
    u32* op = out + (long long)blockIdx.z * sOut;
    const int x0 = blockIdx.x * 32, y0 = blockIdx.y * 32;
    const int tx = threadIdx.x & 31, ty = threadIdx.x >> 5;
    #pragma unroll
    for (int j = 0; j < 32; j += 8)
        sm[ty + j][tx] = ip[(long long)(y0 + ty + j) * Cc + x0 + tx];
    __syncthreads();
    #pragma unroll
    for (int j = 0; j < 32; j += 8)
        op[(long long)(x0 + ty + j) * R + y0 + tx] = pack_hl(sm[tx][ty + j]);
}

// ---------------- softmax row 2048, fp32 in -> packed out ----------------
__global__ void __launch_bounds__(256)
softmax_pack_k(const float* __restrict__ sc, u32* __restrict__ outp){
    const long long row = blockIdx.x;
    const float* p = sc + row * (long long)CS;
    u32* o = outp + row * (long long)CS;
    const int tid = threadIdx.x;
    __shared__ float sm[8];
    float v[8], mx = -3.4e38f;
    #pragma unroll
    for (int i = 0; i < 8; i++){ v[i] = p[tid + i*256]; mx = fmaxf(mx, v[i]); }
    #pragma unroll
    for (int w = 16; w; w >>= 1) mx = fmaxf(mx, __shfl_xor_sync(~0u, mx, w));
    if ((tid & 31) == 0) sm[tid >> 5] = mx;
    __syncthreads();
    if (tid < 32){
        float t = (tid < 8) ? sm[tid] : -3.4e38f;
        #pragma unroll
        for (int w = 4; w; w >>= 1) t = fmaxf(t, __shfl_xor_sync(~0u, t, w));
        if (tid == 0) sm[0] = t;
    }
    __syncthreads(); mx = sm[0]; __syncthreads();
    float s = 0.f;
    #pragma unroll
    for (int i = 0; i < 8; i++){ v[i] = __expf(v[i] - mx); s += v[i]; }
    #pragma unroll
    for (int w = 16; w; w >>= 1) s += __shfl_xor_sync(~0u, s, w);
    if ((tid & 31) == 0) sm[tid >> 5] = s;
    __syncthreads();
    if (tid < 32){
        float t = (tid < 8) ? sm[tid] : 0.f;
        #pragma unroll
        for (int w = 4; w; w >>= 1) t += __shfl_xor_sync(~0u, t, w);
        if (tid == 0) sm[0] = t;
    }
    __syncthreads();
    const float inv = 1.0f / sm[0];
    #pragma unroll
    for (int i = 0; i < 8; i++) o[tid + i*256] = pack_hl(v[i] * inv);
}

// ---------------- out = LN(x+y)*g+b (+packed copy) ----------------
template<bool PK>
__global__ void __launch_bounds__(256)
add_ln_k(const float* __restrict__ x, const float* __restrict__ y,
         const float* __restrict__ g, const float* __restrict__ b,
         float* __restrict__ out, u32* __restrict__ outp){
    const long long row = blockIdx.x;
    const float* px = x + row * (long long)CD;
    const float* py = y + row * (long long)CD;
    float* po = out + row * (long long)CD;
    const int tid = threadIdx.x;
    __shared__ float sm[16];
    float v[4], s = 0.f, s2 = 0.f;
    #pragma unroll
    for (int i = 0; i < 4; i++){
        float t = px[tid + i*256] + py[tid + i*256];
        v[i] = t; s += t; s2 += t*t;
    }
    #pragma unroll
    for (int w = 16; w; w >>= 1){ s += __shfl_xor_sync(~0u, s, w); s2 += __shfl_xor_sync(~0u, s2, w); }
    if ((tid & 31) == 0){ sm[tid>>5] = s; sm[8 + (tid>>5)] = s2; }
    __syncthreads();
    if (tid < 32){
        float t = (tid < 8) ? sm[tid] : 0.f, t2 = (tid < 8) ? sm[8+tid] : 0.f;
        #pragma unroll
        for (int w = 4; w; w >>= 1){ t += __shfl_xor_sync(~0u, t, w); t2 += __shfl_xor_sync(~0u, t2, w); }
        if (tid == 0){ sm[0] = t; sm[8] = t2; }
    }
    __syncthreads();
    const float mean = sm[0] * (1.0f/CD);
    const float var  = sm[8] * (1.0f/CD) - mean*mean;
    const float rs = rsqrtf(var + 1e-5f);
    #pragma unroll
    for (int i = 0; i < 4; i++){
        const int c = tid + i*256;
        const float o = (v[i] - mean) * rs * g[c] + b[c];
        po[c] = o;
        if (PK) outp[row * (long long)CD + c] = pack_hl(o);
    }
}

// ---------------- kernel_launch ----------------
extern "C" void kernel_launch(void* const* d_in, const int* in_sizes, int n_in,
                              void* d_out, int out_size)
{
    const float* x  = (const float*)d_in[0];
    const float* Wq = (const float*)d_in[1];
    const float* Wk = (const float*)d_in[2];
    const float* Wv = (const float*)d_in[3];
    const float* Wo = (const float*)d_in[4];
    const float* bo = (const float*)d_in[5];
    const float* w1 = (const float*)d_in[6];
    const float* b1 = (const float*)d_in[7];
    const float* w2 = (const float*)d_in[8];
    const float* b2 = (const float*)d_in[9];
    const float* w3 = (const float*)d_in[10];
    const float* b3 = (const float*)d_in[11];
    const float* w4 = (const float*)d_in[12];
    const float* b4 = (const float*)d_in[13];
    const float* g1 = (const float*)d_in[14];
    const float* be1= (const float*)d_in[15];
    const float* g2 = (const float*)d_in[16];
    const float* be2= (const float*)d_in[17];
    float* out = (float*)d_out;

    u32 *Xp,*TWq,*TWk,*TWv,*TWo,*Tw1,*Tw2,*Tw3,*Tw4,*Qp,*Kp,*VTp,*ATp,*ZCp,*Y1p,*Y2p,*Z1p;
    float *SC,*AO,*Z1;
    cudaGetSymbolAddress((void**)&Xp, g_Xp);   cudaGetSymbolAddress((void**)&TWq, g_TWq);
    cudaGetSymbolAddress((void**)&TWk, g_TWk); cudaGetSymbolAddress((void**)&TWv, g_TWv);
    cudaGetSymbolAddress((void**)&TWo, g_TWo); cudaGetSymbolAddress((void**)&Tw1, g_Tw1);
    cudaGetSymbolAddress((void**)&Tw2, g_Tw2); cudaGetSymbolAddress((void**)&Tw3, g_Tw3);
    cudaGetSymbolAddress((void**)&Tw4, g_Tw4); cudaGetSymbolAddress((void**)&Qp, g_Qp);
    cudaGetSymbolAddress((void**)&Kp, g_Kp2);  cudaGetSymbolAddress((void**)&VTp, g_VTp);
    cudaGetSymbolAddress((void**)&SC, g_SC);   cudaGetSymbolAddress((void**)&ATp, g_ATp);
    cudaGetSymbolAddress((void**)&ZCp, g_ZCp); cudaGetSymbolAddress((void**)&Y1p, g_Y1p);
    cudaGetSymbolAddress((void**)&Y2p, g_Y2p); cudaGetSymbolAddress((void**)&AO, g_AO);
    cudaGetSymbolAddress((void**)&Z1, g_Z1);   cudaGetSymbolAddress((void**)&Z1p, g_Z1p);

    cudaFuncSetAttribute(tgemm<0,false,false>, cudaFuncAttributeMaxDynamicSharedMemorySize, TG_SMEM);
    cudaFuncSetAttribute(tgemm<1,false,false>, cudaFuncAttributeMaxDynamicSharedMemorySize, TG_SMEM);
    cudaFuncSetAttribute(tgemm<2,false,false>, cudaFuncAttributeMaxDynamicSharedMemorySize, TG_SMEM);
    cudaFuncSetAttribute(tgemm<0,true,false>,  cudaFuncAttributeMaxDynamicSharedMemorySize, TG_SMEM);
    cudaFuncSetAttribute(tgemm<1,true,true>,   cudaFuncAttributeMaxDynamicSharedMemorySize, TG_SMEM);

    const int MT = CB * CS;                       // 8192
    const long long DD  = (long long)CD * CD;
    const long long HBD = (long long)CB * CS * CD;
    const long long SD  = (long long)CS * CD;
    const long long SS  = (long long)CS * CS;

    // ---- prep: pack x, transpose+pack weights ----
    conv_pack_k<<<MT * CD / 256, 256>>>(x, Xp);
    transp_pack_k<<<dim3(32, 32, CH), 256>>>(Wq, TWq, CD, CD, DD, DD);
    transp_pack_k<<<dim3(32, 32, CH), 256>>>(Wk, TWk, CD, CD, DD, DD);
    transp_pack_k<<<dim3(32, 32, CH), 256>>>(Wv, TWv, CD, CD, DD, DD);
    transp_pack_k<<<dim3(32, 256, 1), 256>>>(Wo, TWo, CH * CD, CD, 0, 0);
    transp_pack_k<<<dim3(128, 32, 1), 256>>>(w1, Tw1, CD, CHID, 0, 0);
    transp_pack_k<<<dim3(128, 128, 1), 256>>>(w2, Tw2, CHID, CHID, 0, 0);
    transp_pack_k<<<dim3(128, 128, 1), 256>>>(w3, Tw3, CHID, CHID, 0, 0);
    transp_pack_k<<<dim3(32, 128, 1), 256>>>(w4, Tw4, CHID, CD, 0, 0);

    // ---- QKV: Xp[8192,1024] x TW[h][1024,1024] ----
    {
        dim3 grid(CD / 128, MT / 128, CH);
        tgemm<1,false,false><<<grid, 256, TG_SMEM>>>(Xp, TWq, Qp, nullptr,
            CD, CD, CD, CD, 0, DD, HBD, 0, 1, 1.0f);
        tgemm<1,false,false><<<grid, 256, TG_SMEM>>>(Xp, TWk, Kp, nullptr,
            CD, CD, CD, CD, 0, DD, HBD, 0, 1, 1.0f);
        tgemm<2,false,false><<<grid, 256, TG_SMEM>>>(Xp, TWv, VTp, nullptr,
            CD, CD, CD, 0, 0, DD, HBD, 0, 1, 1.0f);
    }
    // ---- scores = Q K^T / 32, per (h,b) ----
    {
        dim3 grid(CS / 128, CS / 128, CH * CB);
        tgemm<0,false,false><<<grid, 256, TG_SMEM>>>(Qp, Kp, SC, nullptr,
            CD, CD, CD, CS, SD, SD, SS, 0, 1, 0.03125f);
    }
    // ---- softmax + pack ----
    softmax_pack_k<<<CH * CB * CS, 256>>>(SC, ATp);
    // ---- Z = attn @ V -> head-concat packed ----
    {
        dim3 grid(CD / 128, CS / 128, CH * CB);
        tgemm<1,false,false><<<grid, 256, TG_SMEM>>>(ATp, VTp, ZCp, nullptr,
            CS, CS, CS, CH * CD, SS, (long long)CD * CS,
            (long long)CD, (long long)CS * CH * CD, CB, 1.0f);
    }
    // ---- attn_out = ZC @ Wo + bo ----
    {
        dim3 grid(CD / 128, MT / 128, 1);
        tgemm<0,true,false><<<grid, 256, TG_SMEM>>>(ZCp, TWo, AO, bo,
            CH * CD, CH * CD, CH * CD, CD, 0, 0, 0, 0, 1, 1.0f);
    }
    // ---- Z1 = LN(x + attn_out) ----
    add_ln_k<true><<<MT, 256>>>(x, AO, g1, be1, Z1, Z1p);
    // ---- FFN ----
    {
        dim3 gh(CHID / 128, MT / 128, 1);
        tgemm<1,true,true><<<gh, 256, TG_SMEM>>>(Z1p, Tw1, Y1p, b1,
            CD, CD, CD, CHID, 0, 0, 0, 0, 1, 1.0f);
        tgemm<1,true,true><<<gh, 256, TG_SMEM>>>(Y1p, Tw2, Y2p, b2,
            CHID, CHID, CHID, CHID, 0, 0, 0, 0, 1, 1.0f);
        tgemm<1,true,true><<<gh, 256, TG_SMEM>>>(Y2p, Tw3, Y1p, b3,
            CHID, CHID, CHID, CHID, 0, 0, 0, 0, 1, 1.0f);
        dim3 g4(CD / 128, MT / 128, 1);
        tgemm<0,true,false><<<g4, 256, TG_SMEM>>>(Y1p, Tw4, AO, b4,
            CHID, CHID, CHID, CD, 0, 0, 0, 0, 1, 1.0f);
    }
    // ---- out = LN(Z1 + ffn_out) ----
    add_ln_k<false><<<MT, 256>>>(Z1, AO, g2, be2, out, nullptr);
}

// round 10
// speedup vs baseline: 3.0833x; 1.1133x over previous
#include <cuda_runtime.h>
#include <cuda_bf16.h>
#include <math.h>

typedef unsigned int u32;
typedef unsigned long long u64;
typedef __nv_bfloat16 bf16;

#define CB 4
#define CS 2048
#define CD 1024
#define CH 8
#define CHID 4096

// ---------------- scratch (device globals) ----------------
// Every GEMM operand has TWO bf16 planes: hi = bf16(x), lo = bf16(x - hi).
// All K-major. Declared as uint4 arrays for 16B alignment (cp.async).
#define DECL_PLANES(name, n) \
    __device__ uint4 name##_h_[(size_t)(n) / 8]; \
    __device__ uint4 name##_l_[(size_t)(n) / 8];

DECL_PLANES(g_X,  (size_t)CB*CS*CD)
DECL_PLANES(g_Wq, (size_t)CH*CD*CD)
DECL_PLANES(g_Wk, (size_t)CH*CD*CD)
DECL_PLANES(g_Wv, (size_t)CH*CD*CD)
DECL_PLANES(g_Wo, (size_t)CD*CH*CD)
DECL_PLANES(g_W1, (size_t)CHID*CD)
DECL_PLANES(g_W2, (size_t)CHID*CHID)
DECL_PLANES(g_W3, (size_t)CHID*CHID)
DECL_PLANES(g_W4, (size_t)CD*CHID)
DECL_PLANES(g_Q,  (size_t)CH*CB*CS*CD)
DECL_PLANES(g_K,  (size_t)CH*CB*CS*CD)
DECL_PLANES(g_VT, (size_t)CH*CB*CD*CS)
DECL_PLANES(g_AT, (size_t)CH*CB*CS*CS)
DECL_PLANES(g_ZC, (size_t)CB*CS*CH*CD)
DECL_PLANES(g_Y1, (size_t)CB*CS*CHID)
DECL_PLANES(g_Y2, (size_t)CB*CS*CHID)
DECL_PLANES(g_ZN, (size_t)CB*CS*CD)
__device__ float g_SC[(size_t)CH*CB*CS*CS];
__device__ float g_AO[(size_t)CB*CS*CD];
__device__ float g_Z1[(size_t)CB*CS*CD];

// ---------------- helpers ----------------
__device__ __forceinline__ u32 smem_u32(const void* p){
    u32 a; asm("{ .reg .u64 t; cvta.to.shared.u64 t, %1; cvt.u32.u64 %0, t; }":"=r"(a):"l"(p)); return a;
}
__device__ __forceinline__ void split2(float v, bf16& h, bf16& l){
    h = __float2bfloat16(v);
    l = __float2bfloat16(v - __bfloat162float(h));
}

__device__ __forceinline__ void cpa16(u32 dst, const void* src){
    asm volatile("cp.async.cg.shared.global [%0], [%1], 16;" :: "r"(dst), "l"(src));
}
#define CP_COMMIT() asm volatile("cp.async.commit_group;" ::: "memory")
#define CP_WAIT1()  asm volatile("cp.async.wait_group 1;" ::: "memory")

#define LDM_X4(r, a) asm volatile( \
    "ldmatrix.sync.aligned.m8n8.x4.shared.b16 {%0,%1,%2,%3}, [%4];" \
    : "=r"((r)[0]),"=r"((r)[1]),"=r"((r)[2]),"=r"((r)[3]) : "r"(a))

#define MMA_BF16(c, a, b0v, b1v) asm volatile( \
    "mma.sync.aligned.m16n8k16.row.col.f32.bf16.bf16.f32 " \
    "{%0,%1,%2,%3},{%4,%5,%6,%7},{%8,%9},{%0,%1,%2,%3};" \
    : "+f"((c)[0]),"+f"((c)[1]),"+f"((c)[2]),"+f"((c)[3]) \
    : "r"((a)[0]),"r"((a)[1]),"r"((a)[2]),"r"((a)[3]), "r"(b0v),"r"(b1v))

// ---------------- mma.sync GEMM: CTA 128x256, warp 64x64, K-chunk 32 ----------------
// 3-stage cp.async pipeline, bf16x3 (hi*hi + hi*lo + lo*hi), fp32 accum.
// D[m][n] = alpha * sum_k A[m][k]*B[n][k] (+bias) (+relu).
// MODE: 0 fp32 out (Cf), 1 two-plane out (Ch/Cl), 2 two-plane transposed out.
#define STG_A_H 0
#define STG_A_L 8192
#define STG_B_H 16384
#define STG_B_L 32768
#define STG_BYTES 49152
#define NSTG 3
#define TG_SMEM (NSTG * STG_BYTES)

template<int MODE, bool BIAS, bool RELU>
__global__ void __launch_bounds__(256, 1)
tgemm(const bf16* __restrict__ Ah, const bf16* __restrict__ Al,
      const bf16* __restrict__ Bh, const bf16* __restrict__ Bl,
      float* __restrict__ Cf, bf16* __restrict__ Ch, bf16* __restrict__ Cl,
      const float* __restrict__ bias,
      int K, int lda, int ldb, int ldc,
      long long sA, long long sB, long long cs1, long long cs2, int cdiv,
      float alpha)
{
    extern __shared__ __align__(16) char smem[];
    const u32 smb = smem_u32(smem);

    const int tid = threadIdx.x, lane = tid & 31, wid = tid >> 5;
    const int wm = wid >> 2, wn = wid & 3;                    // 2m x 4n warps, 64x64 each
    const int z = blockIdx.z, m0 = blockIdx.y * 128, n0 = blockIdx.x * 256;

    Ah += (long long)z * sA + (long long)m0 * lda;
    Al += (long long)z * sA + (long long)m0 * lda;
    Bh += (long long)z * sB + (long long)n0 * ldb;
    Bl += (long long)z * sB + (long long)n0 * ldb;
    const long long coff = (long long)(z / cdiv) * cs1 + (long long)(z % cdiv) * cs2;

    float acc[4][8][4];
    #pragma unroll
    for (int i = 0; i < 4; i++)
        #pragma unroll
        for (int j = 0; j < 8; j++)
            #pragma unroll
            for (int q = 0; q < 4; q++) acc[i][j][q] = 0.f;

    const int NT = K >> 5;

    // cp.async issue for chunk cc into its stage. 16B granules; smem rows = 64B.
    #define ISSUE(cc) do { \
        const int kb = (cc) * 32; \
        const u32 stg_ = smb + (u32)((cc) % NSTG) * STG_BYTES; \
        _Pragma("unroll") \
        for (int t2 = 0; t2 < 2; t2++) { \
            const int task = t2 * 256 + tid; \
            const int row = task >> 2, seg = task & 3; \
            const u32 d_ = (u32)row * 64 + ((u32)(seg ^ ((row >> 1) & 3)) << 4); \
            cpa16(stg_ + STG_A_H + d_, Ah + (long long)row * lda + kb + seg * 8); \
            cpa16(stg_ + STG_A_L + d_, Al + (long long)row * lda + kb + seg * 8); \
        } \
        _Pragma("unroll") \
        for (int t4 = 0; t4 < 4; t4++) { \
            const int task = t4 * 256 + tid; \
            const int row = task >> 2, seg = task & 3; \
            const u32 d_ = (u32)row * 64 + ((u32)(seg ^ ((row >> 1) & 3)) << 4); \
            cpa16(stg_ + STG_B_H + d_, Bh + (long long)row * ldb + kb + seg * 8); \
            cpa16(stg_ + STG_B_L + d_, Bl + (long long)row * ldb + kb + seg * 8); \
        } \
        CP_COMMIT(); \
    } while (0)

    ISSUE(0);
    ISSUE(1);

    for (int c = 0; c < NT; c++) {
        CP_WAIT1();
        __syncthreads();
        const u32 stg = smb + (u32)(c % NSTG) * STG_BYTES;

        #pragma unroll
        for (int kk = 0; kk < 2; kk++) {
            u32 ah[4][4], al[4][4];
            const int arow = wm * 64 + (lane & 15);
            const int aks  = kk * 2 + (lane >> 4);
            #pragma unroll
            for (int mt = 0; mt < 4; mt++) {
                const int ro = arow + mt * 16;
                const u32 off = (u32)ro * 64 + ((u32)(aks ^ ((ro >> 1) & 3)) << 4);
                LDM_X4(ah[mt], stg + STG_A_H + off);
                LDM_X4(al[mt], stg + STG_A_L + off);
            }
            const int brow0 = wn * 64 + ((lane >> 4) & 1) * 8 + (lane & 7);
            const int bks = kk * 2 + ((lane >> 3) & 1);
            #pragma unroll
            for (int np = 0; np < 4; np++) {
                const int ro = brow0 + np * 16;
                const u32 off = (u32)ro * 64 + ((u32)(bks ^ ((ro >> 1) & 3)) << 4);
                u32 th[4], tl[4];
                LDM_X4(th, stg + STG_B_H + off);
                LDM_X4(tl, stg + STG_B_L + off);
                #pragma unroll
                for (int mt = 0; mt < 4; mt++) {
                    MMA_BF16(acc[mt][np*2],   ah[mt], th[0], th[1]);
                    MMA_BF16(acc[mt][np*2+1], ah[mt], th[2], th[3]);
                    MMA_BF16(acc[mt][np*2],   ah[mt], tl[0], tl[1]);
                    MMA_BF16(acc[mt][np*2+1], ah[mt], tl[2], tl[3]);
                    MMA_BF16(acc[mt][np*2],   al[mt], th[0], th[1]);
                    MMA_BF16(acc[mt][np*2+1], al[mt], th[2], th[3]);
                }
            }
        }

        if (c + 2 < NT) { ISSUE(c + 2); } else { CP_COMMIT(); }
        __syncthreads();
    }
    #undef ISSUE

    // ---- epilogue: frag map rows lane>>2 (+8), cols (lane&3)*2 ----
    const int er = lane >> 2, ec = (lane & 3) * 2;
    #pragma unroll
    for (int mt = 0; mt < 4; mt++) {
        #pragma unroll
        for (int nt = 0; nt < 8; nt++) {
            const float* a4 = acc[mt][nt];
            const int row0 = m0 + wm * 64 + mt * 16 + er;
            const int col  = n0 + wn * 64 + nt * 8 + ec;
            float v00 = a4[0] * alpha, v01 = a4[1] * alpha;
            float v10 = a4[2] * alpha, v11 = a4[3] * alpha;
            if (BIAS) {
                const float bb0 = bias[col], bb1 = bias[col + 1];
                v00 += bb0; v01 += bb1; v10 += bb0; v11 += bb1;
            }
            if (RELU) {
                v00 = fmaxf(v00, 0.f); v01 = fmaxf(v01, 0.f);
                v10 = fmaxf(v10, 0.f); v11 = fmaxf(v11, 0.f);
            }
            if (MODE == 0) {
                float* C = Cf + coff;
                *(float2*)(C + (long long)row0 * ldc + col)       = make_float2(v00, v01);
                *(float2*)(C + (long long)(row0 + 8) * ldc + col) = make_float2(v10, v11);
            } else if (MODE == 1) {
                bf16 h0, l0, h1, l1;
                __nv_bfloat162 ph, pl;
                split2(v00, h0, l0); split2(v01, h1, l1);
                ph.x = h0; ph.y = h1; pl.x = l0; pl.y = l1;
                *(__nv_bfloat162*)(Ch + coff + (long long)row0 * ldc + col) = ph;
                *(__nv_bfloat162*)(Cl + coff + (long long)row0 * ldc + col) = pl;
                split2(v10, h0, l0); split2(v11, h1, l1);
                ph.x = h0; ph.y = h1; pl.x = l0; pl.y = l1;
                *(__nv_bfloat162*)(Ch + coff + (long long)(row0 + 8) * ldc + col) = ph;
                *(__nv_bfloat162*)(Cl + coff + (long long)(row0 + 8) * ldc + col) = pl;
            } else {
                // transposed: addr(e, token) = coff + (tok>>11)*(CD*CS) + (tok&2047) + e*CS
                const long long o0 = coff + (long long)(row0 >> 11) * ((long long)CD * CS) + (row0 & (CS - 1));
                const int r1 = row0 + 8;
                const long long o1 = coff + (long long)(r1 >> 11) * ((long long)CD * CS) + (r1 & (CS - 1));
                bf16 h, l;
                split2(v00, h, l); Ch[o0 + (long long)col * CS] = h;       Cl[o0 + (long long)col * CS] = l;
                split2(v01, h, l); Ch[o0 + (long long)(col + 1) * CS] = h; Cl[o0 + (long long)(col + 1) * CS] = l;
                split2(v10, h, l); Ch[o1 + (long long)col * CS] = h;       Cl[o1 + (long long)col * CS] = l;
                split2(v11, h, l); Ch[o1 + (long long)(col + 1) * CS] = h; Cl[o1 + (long long)(col + 1) * CS] = l;
            }
        }
    }
}

// ---------------- fp32 -> two planes ----------------
__global__ void __launch_bounds__(256)
conv_pack_k(const float* __restrict__ in, bf16* __restrict__ oh, bf16* __restrict__ ol){
    const long long i = (long long)blockIdx.x * 256 + threadIdx.x;
    bf16 h, l; split2(in[i], h, l);
    oh[i] = h; ol[i] = l;
}

// ---------------- fp32 [R,C] -> two planes [C,R] (batched) ----------------
__global__ void __launch_bounds__(256)
transp_pack_k(const float* __restrict__ in, bf16* __restrict__ oh, bf16* __restrict__ ol,
              int R, int Cc, long long sIn, long long sOut){
    __shared__ float sm[32][33];
    const float* ip = in + (long long)blockIdx.z * sIn;
    bf16* oph = oh + (long long)blockIdx.z * sOut;
    bf16* opl = ol + (long long)blockIdx.z * sOut;
    const int x0 = blockIdx.x * 32, y0 = blockIdx.y * 32;
    const int tx = threadIdx.x & 31, ty = threadIdx.x >> 5;
    #pragma unroll
    for (int j = 0; j < 32; j += 8)
        sm[ty + j][tx] = ip[(long long)(y0 + ty + j) * Cc + x0 + tx];
    __syncthreads();
    #pragma unroll
    for (int j = 0; j < 32; j += 8) {
        bf16 h, l; split2(sm[tx][ty + j], h, l);
        const long long o = (long long)(x0 + ty + j) * R + y0 + tx;
        oph[o] = h; opl[o] = l;
    }
}

// ---------------- softmax row 2048, fp32 in -> two planes out ----------------
__global__ void __launch_bounds__(256)
softmax_pack_k(const float* __restrict__ sc, bf16* __restrict__ oh, bf16* __restrict__ ol){
    const long long row = blockIdx.x;
    const float* p = sc + row * (long long)CS;
    bf16* o_h = oh + row * (long long)CS;
    bf16* o_l = ol + row * (long long)CS;
    const int tid = threadIdx.x;
    __shared__ float sm[8];
    float v[8], mx = -3.4e38f;
    #pragma unroll
    for (int i = 0; i < 8; i++){ v[i] = p[tid + i*256]; mx = fmaxf(mx, v[i]); }
    #pragma unroll
    for (int w = 16; w; w >>= 1) mx = fmaxf(mx, __shfl_xor_sync(~0u, mx, w));
    if ((tid & 31) == 0) sm[tid >> 5] = mx;
    __syncthreads();
    if (tid < 32){
        float t = (tid < 8) ? sm[tid] : -3.4e38f;
        #pragma unroll
        for (int w = 4; w; w >>= 1) t = fmaxf(t, __shfl_xor_sync(~0u, t, w));
        if (tid == 0) sm[0] = t;
    }
    __syncthreads(); mx = sm[0]; __syncthreads();
    float s = 0.f;
    #pragma unroll
    for (int i = 0; i < 8; i++){ v[i] = __expf(v[i] - mx); s += v[i]; }
    #pragma unroll
    for (int w = 16; w; w >>= 1) s += __shfl_xor_sync(~0u, s, w);
    if ((tid & 31) == 0) sm[tid >> 5] = s;
    __syncthreads();
    if (tid < 32){
        float t = (tid < 8) ? sm[tid] : 0.f;
        #pragma unroll
        for (int w = 4; w; w >>= 1) t += __shfl_xor_sync(~0u, t, w);
        if (tid == 0) sm[0] = t;
    }
    __syncthreads();
    const float inv = 1.0f / sm[0];
    #pragma unroll
    for (int i = 0; i < 8; i++){
        bf16 h, l; split2(v[i] * inv, h, l);
        o_h[tid + i*256] = h; o_l[tid + i*256] = l;
    }
}

// ---------------- out = LN(x+y)*g+b (+two-plane copy) ----------------
template<bool PK>
__global__ void __launch_bounds__(256)
add_ln_k(const float* __restrict__ x, const float* __restrict__ y,
         const float* __restrict__ g, const float* __restrict__ b,
         float* __restrict__ out, bf16* __restrict__ oh, bf16* __restrict__ ol){
    const long long row = blockIdx.x;
    const float* px = x + row * (long long)CD;
    const float* py = y + row * (long long)CD;
    float* po = out + row * (long long)CD;
    const int tid = threadIdx.x;
    __shared__ float sm[16];
    float v[4], s = 0.f, s2 = 0.f;
    #pragma unroll
    for (int i = 0; i < 4; i++){
        float t = px[tid + i*256] + py[tid + i*256];
        v[i] = t; s += t; s2 += t*t;
    }
    #pragma unroll
    for (int w = 16; w; w >>= 1){ s += __shfl_xor_sync(~0u, s, w); s2 += __shfl_xor_sync(~0u, s2, w); }
    if ((tid & 31) == 0){ sm[tid>>5] = s; sm[8 + (tid>>5)] = s2; }
    __syncthreads();
    if (tid < 32){
        float t = (tid < 8) ? sm[tid] : 0.f, t2 = (tid < 8) ? sm[8+tid] : 0.f;
        #pragma unroll
        for (int w = 4; w; w >>= 1){ t += __shfl_xor_sync(~0u, t, w); t2 += __shfl_xor_sync(~0u, t2, w); }
        if (tid == 0){ sm[0] = t; sm[8] = t2; }
    }
    __syncthreads();
    const float mean = sm[0] * (1.0f/CD);
    const float var  = sm[8] * (1.0f/CD) - mean*mean;
    const float rs = rsqrtf(var + 1e-5f);
    #pragma unroll
    for (int i = 0; i < 4; i++){
        const int c = tid + i*256;
        const float o = (v[i] - mean) * rs * g[c] + b[c];
        po[c] = o;
        if (PK) {
            bf16 h, l; split2(o, h, l);
            oh[row * (long long)CD + c] = h;
            ol[row * (long long)CD + c] = l;
        }
    }
}

// ---------------- kernel_launch ----------------
#define GETP(sym, vh, vl) \
    cudaGetSymbolAddress((void**)&vh, sym##_h_); \
    cudaGetSymbolAddress((void**)&vl, sym##_l_);

extern "C" void kernel_launch(void* const* d_in, const int* in_sizes, int n_in,
                              void* d_out, int out_size)
{
    const float* x  = (const float*)d_in[0];
    const float* Wq = (const float*)d_in[1];
    const float* Wk = (const float*)d_in[2];
    const float* Wv = (const float*)d_in[3];
    const float* Wo = (const float*)d_in[4];
    const float* bo = (const float*)d_in[5];
    const float* w1 = (const float*)d_in[6];
    const float* b1 = (const float*)d_in[7];
    const float* w2 = (const float*)d_in[8];
    const float* b2 = (const float*)d_in[9];
    const float* w3 = (const float*)d_in[10];
    const float* b3 = (const float*)d_in[11];
    const float* w4 = (const float*)d_in[12];
    const float* b4 = (const float*)d_in[13];
    const float* g1 = (const float*)d_in[14];
    const float* be1= (const float*)d_in[15];
    const float* g2 = (const float*)d_in[16];
    const float* be2= (const float*)d_in[17];
    float* out = (float*)d_out;

    bf16 *Xh,*Xl,*Wqh,*Wql,*Wkh,*Wkl,*Wvh,*Wvl,*Woh,*Wol;
    bf16 *W1h,*W1l,*W2h,*W2l,*W3h,*W3l,*W4h,*W4l;
    bf16 *Qh,*Ql,*Kh,*Kl,*VTh,*VTl,*ATh,*ATl,*ZCh,*ZCl;
    bf16 *Y1h,*Y1l,*Y2h,*Y2l,*ZNh,*ZNl;
    float *SC,*AO,*Z1;
    GETP(g_X, Xh, Xl)   GETP(g_Wq, Wqh, Wql) GETP(g_Wk, Wkh, Wkl)
    GETP(g_Wv, Wvh, Wvl) GETP(g_Wo, Woh, Wol)
    GETP(g_W1, W1h, W1l) GETP(g_W2, W2h, W2l) GETP(g_W3, W3h, W3l) GETP(g_W4, W4h, W4l)
    GETP(g_Q, Qh, Ql)   GETP(g_K, Kh, Kl)   GETP(g_VT, VTh, VTl)
    GETP(g_AT, ATh, ATl) GETP(g_ZC, ZCh, ZCl)
    GETP(g_Y1, Y1h, Y1l) GETP(g_Y2, Y2h, Y2l) GETP(g_ZN, ZNh, ZNl)
    cudaGetSymbolAddress((void**)&SC, g_SC);
    cudaGetSymbolAddress((void**)&AO, g_AO);
    cudaGetSymbolAddress((void**)&Z1, g_Z1);

    cudaFuncSetAttribute(tgemm<0,false,false>, cudaFuncAttributeMaxDynamicSharedMemorySize, TG_SMEM);
    cudaFuncSetAttribute(tgemm<1,false,false>, cudaFuncAttributeMaxDynamicSharedMemorySize, TG_SMEM);
    cudaFuncSetAttribute(tgemm<2,false,false>, cudaFuncAttributeMaxDynamicSharedMemorySize, TG_SMEM);
    cudaFuncSetAttribute(tgemm<0,true,false>,  cudaFuncAttributeMaxDynamicSharedMemorySize, TG_SMEM);
    cudaFuncSetAttribute(tgemm<1,true,true>,   cudaFuncAttributeMaxDynamicSharedMemorySize, TG_SMEM);

    const int MT = CB * CS;                       // 8192
    const long long DD  = (long long)CD * CD;
    const long long HBD = (long long)CB * CS * CD;
    const long long SD  = (long long)CS * CD;
    const long long SS  = (long long)CS * CS;

    // ---- prep: pack x, transpose+pack weights ----
    conv_pack_k<<<MT * CD / 256, 256>>>(x, Xh, Xl);
    transp_pack_k<<<dim3(32, 32, CH), 256>>>(Wq, Wqh, Wql, CD, CD, DD, DD);
    transp_pack_k<<<dim3(32, 32, CH), 256>>>(Wk, Wkh, Wkl, CD, CD, DD, DD);
    transp_pack_k<<<dim3(32, 32, CH), 256>>>(Wv, Wvh, Wvl, CD, CD, DD, DD);
    transp_pack_k<<<dim3(32, 256, 1), 256>>>(Wo, Woh, Wol, CH * CD, CD, 0, 0);
    transp_pack_k<<<dim3(128, 32, 1), 256>>>(w1, W1h, W1l, CD, CHID, 0, 0);
    transp_pack_k<<<dim3(128, 128, 1), 256>>>(w2, W2h, W2l, CHID, CHID, 0, 0);
    transp_pack_k<<<dim3(128, 128, 1), 256>>>(w3, W3h, W3l, CHID, CHID, 0, 0);
    transp_pack_k<<<dim3(32, 128, 1), 256>>>(w4, W4h, W4l, CHID, CD, 0, 0);

    // ---- QKV: X[8192,1024] x W[h][1024,1024] ----
    {
        dim3 grid(CD / 256, MT / 128, CH);
        tgemm<1,false,false><<<grid, 256, TG_SMEM>>>(Xh, Xl, Wqh, Wql,
            nullptr, Qh, Ql, nullptr, CD, CD, CD, CD, 0, DD, HBD, 0, 1, 1.0f);
        tgemm<1,false,false><<<grid, 256, TG_SMEM>>>(Xh, Xl, Wkh, Wkl,
            nullptr, Kh, Kl, nullptr, CD, CD, CD, CD, 0, DD, HBD, 0, 1, 1.0f);
        tgemm<2,false,false><<<grid, 256, TG_SMEM>>>(Xh, Xl, Wvh, Wvl,
            nullptr, VTh, VTl, nullptr, CD, CD, CD, 0, 0, DD, HBD, 0, 1, 1.0f);
    }
    // ---- scores = Q K^T / 32, per (h,b) ----
    {
        dim3 grid(CS / 256, CS / 128, CH * CB);
        tgemm<0,false,false><<<grid, 256, TG_SMEM>>>(Qh, Ql, Kh, Kl,
            SC, nullptr, nullptr, nullptr, CD, CD, CD, CS, SD, SD, SS, 0, 1, 0.03125f);
    }
    // ---- softmax + pack ----
    softmax_pack_k<<<CH * CB * CS, 256>>>(SC, ATh, ATl);
    // ---- Z = attn @ V -> head-concat packed ----
    {
        dim3 grid(CD / 256, CS / 128, CH * CB);
        tgemm<1,false,false><<<grid, 256, TG_SMEM>>>(ATh, ATl, VTh, VTl,
            nullptr, ZCh, ZCl, nullptr, CS, CS, CS, CH * CD, SS, (long long)CD * CS,
            (long long)CD, (long long)CS * CH * CD, CB, 1.0f);
    }
    // ---- attn_out = ZC @ Wo + bo ----
    {
        dim3 grid(CD / 256, MT / 128, 1);
        tgemm<0,true,false><<<grid, 256, TG_SMEM>>>(ZCh, ZCl, Woh, Wol,
            AO, nullptr, nullptr, bo, CH * CD, CH * CD, CH * CD, CD, 0, 0, 0, 0, 1, 1.0f);
    }
    // ---- Z1 = LN(x + attn_out) ----
    add_ln_k<true><<<MT, 256>>>(x, AO, g1, be1, Z1, ZNh, ZNl);
    // ---- FFN ----
    {
        dim3 gh(CHID / 256, MT / 128, 1);
        tgemm<1,true,true><<<gh, 256, TG_SMEM>>>(ZNh, ZNl, W1h, W1l,
            nullptr, Y1h, Y1l, b1, CD, CD, CD, CHID, 0, 0, 0, 0, 1, 1.0f);
        tgemm<1,true,true><<<gh, 256, TG_SMEM>>>(Y1h, Y1l, W2h, W2l,
            nullptr, Y2h, Y2l, b2, CHID, CHID, CHID, CHID, 0, 0, 0, 0, 1, 1.0f);
        tgemm<1,true,true><<<gh, 256, TG_SMEM>>>(Y2h, Y2l, W3h, W3l,
            nullptr, Y1h, Y1l, b3, CHID, CHID, CHID, CHID, 0, 0, 0, 0, 1, 1.0f);
        dim3 g4(CD / 256, MT / 128, 1);
        tgemm<0,true,false><<<g4, 256, TG_SMEM>>>(Y1h, Y1l, W4h, W4l,
            AO, nullptr, nullptr, b4, CHID, CHID, CHID, CD, 0, 0, 0, 0, 1, 1.0f);
    }
    // ---- out = LN(Z1 + ffn_out) ----
    add_ln_k<false><<<MT, 256>>>(Z1, AO, g2, be2, out, nullptr, nullptr);
}

// round 11
// speedup vs baseline: 4.8464x; 1.5718x over previous
#include <cuda_runtime.h>
#include <cuda_bf16.h>
#include <math.h>

typedef unsigned int u32;
typedef unsigned long long u64;
typedef __nv_bfloat16 bf16;

#define CB 4
#define CS 2048
#define CD 1024
#define CH 8
#define CHID 4096

// ---------------- scratch (device globals) ----------------
// FFN tensors: TWO bf16 planes (hi = bf16(x), lo = bf16(x-hi)) for bf16x3.
// Attention tensors: hi plane only (bf16x1). All K-major, uint4 for 16B align.
#define DECL_PLANES(name, n) \
    __device__ uint4 name##_h_[(size_t)(n) / 8]; \
    __device__ uint4 name##_l_[(size_t)(n) / 8];
#define DECL_ONE(name, n) __device__ uint4 name##_h_[(size_t)(n) / 8];

DECL_ONE(g_X,  (size_t)CB*CS*CD)
DECL_ONE(g_Wq, (size_t)CH*CD*CD)
DECL_ONE(g_Wk, (size_t)CH*CD*CD)
DECL_ONE(g_Wv, (size_t)CH*CD*CD)
DECL_ONE(g_Wo, (size_t)CD*CH*CD)
DECL_PLANES(g_W1, (size_t)CHID*CD)
DECL_PLANES(g_W2, (size_t)CHID*CHID)
DECL_PLANES(g_W3, (size_t)CHID*CHID)
DECL_PLANES(g_W4, (size_t)CD*CHID)
DECL_ONE(g_Q,  (size_t)CH*CB*CS*CD)     // [(h,b)][s][d] hi
DECL_ONE(g_K,  (size_t)CH*CB*CS*CD)
DECL_ONE(g_VT, (size_t)CH*CB*CD*CS)     // [h][b][e][t] hi
DECL_ONE(g_SCb,(size_t)CH*CB*CS*CS)     // scores bf16
DECL_ONE(g_AT, (size_t)CH*CB*CS*CS)     // attn hi
DECL_ONE(g_ZC, (size_t)CB*CS*CH*CD)     // head-concat hi
DECL_PLANES(g_Y1, (size_t)CB*CS*CHID)
DECL_PLANES(g_Y2, (size_t)CB*CS*CHID)
DECL_PLANES(g_ZN, (size_t)CB*CS*CD)
__device__ float g_AO[(size_t)CB*CS*CD];
__device__ float g_Z1[(size_t)CB*CS*CD];

// ---------------- helpers ----------------
__device__ __forceinline__ u32 smem_u32(const void* p){
    u32 a; asm("{ .reg .u64 t; cvta.to.shared.u64 t, %1; cvt.u32.u64 %0, t; }":"=r"(a):"l"(p)); return a;
}
__device__ __forceinline__ void split2(float v, bf16& h, bf16& l){
    h = __float2bfloat16(v);
    l = __float2bfloat16(v - __bfloat162float(h));
}
__device__ __forceinline__ void cpa16(u32 dst, const void* src){
    asm volatile("cp.async.cg.shared.global [%0], [%1], 16;" :: "r"(dst), "l"(src));
}
#define CP_COMMIT() asm volatile("cp.async.commit_group;" ::: "memory")
#define CP_WAIT1()  asm volatile("cp.async.wait_group 1;" ::: "memory")

#define LDM_X4(r, a) asm volatile( \
    "ldmatrix.sync.aligned.m8n8.x4.shared.b16 {%0,%1,%2,%3}, [%4];" \
    : "=r"((r)[0]),"=r"((r)[1]),"=r"((r)[2]),"=r"((r)[3]) : "r"(a))

#define MMA_BF16(c, a, b0v, b1v) asm volatile( \
    "mma.sync.aligned.m16n8k16.row.col.f32.bf16.bf16.f32 " \
    "{%0,%1,%2,%3},{%4,%5,%6,%7},{%8,%9},{%0,%1,%2,%3};" \
    : "+f"((c)[0]),"+f"((c)[1]),"+f"((c)[2]),"+f"((c)[3]) \
    : "r"((a)[0]),"r"((a)[1]),"r"((a)[2]),"r"((a)[3]), "r"(b0v),"r"(b1v))

// ---------------- mma.sync GEMM: CTA 128x256, warp 64x64, K-chunk 32 ----------------
// 3-stage cp.async pipeline. PASSES: 1 = bf16 (hi*hi), 3 = bf16x3.
// MODE: 0 fp32 out; 1 two-plane out; 2 single-plane row-major; 3 single-plane transposed.
#define STG_A_H 0
#define STG_A_L 8192
#define STG_B_H 16384
#define STG_B_L 32768
#define STG_BYTES 49152
#define NSTG 3
#define TG_SMEM (NSTG * STG_BYTES)

template<int PASSES, int MODE, bool BIAS, bool RELU>
__global__ void __launch_bounds__(256, 1)
tgemm(const bf16* __restrict__ Ah, const bf16* __restrict__ Al,
      const bf16* __restrict__ Bh, const bf16* __restrict__ Bl,
      float* __restrict__ Cf, bf16* __restrict__ Ch, bf16* __restrict__ Cl,
      const float* __restrict__ bias,
      int K, int lda, int ldb, int ldc,
      long long sA, long long sB, long long cs1, long long cs2, int cdiv,
      float alpha)
{
    extern __shared__ __align__(16) char smem[];
    const u32 smb = smem_u32(smem);

    const int tid = threadIdx.x, lane = tid & 31, wid = tid >> 5;
    const int wm = wid >> 2, wn = wid & 3;                    // 2m x 4n warps, 64x64 each
    const int z = blockIdx.z, m0 = blockIdx.y * 128, n0 = blockIdx.x * 256;

    Ah += (long long)z * sA + (long long)m0 * lda;
    Bh += (long long)z * sB + (long long)n0 * ldb;
    if (PASSES == 3) {
        Al += (long long)z * sA + (long long)m0 * lda;
        Bl += (long long)z * sB + (long long)n0 * ldb;
    }
    const long long coff = (long long)(z / cdiv) * cs1 + (long long)(z % cdiv) * cs2;

    float acc[4][8][4];
    #pragma unroll
    for (int i = 0; i < 4; i++)
        #pragma unroll
        for (int j = 0; j < 8; j++)
            #pragma unroll
            for (int q = 0; q < 4; q++) acc[i][j][q] = 0.f;

    const int NT = K >> 5;

    #define ISSUE(cc) do { \
        const int kb = (cc) * 32; \
        const u32 stg_ = smb + (u32)((cc) % NSTG) * STG_BYTES; \
        _Pragma("unroll") \
        for (int t2 = 0; t2 < 2; t2++) { \
            const int task = t2 * 256 + tid; \
            const int row = task >> 2, seg = task & 3; \
            const u32 d_ = (u32)row * 64 + ((u32)(seg ^ ((row >> 1) & 3)) << 4); \
            cpa16(stg_ + STG_A_H + d_, Ah + (long long)row * lda + kb + seg * 8); \
            if (PASSES == 3) cpa16(stg_ + STG_A_L + d_, Al + (long long)row * lda + kb + seg * 8); \
        } \
        _Pragma("unroll") \
        for (int t4 = 0; t4 < 4; t4++) { \
            const int task = t4 * 256 + tid; \
            const int row = task >> 2, seg = task & 3; \
            const u32 d_ = (u32)row * 64 + ((u32)(seg ^ ((row >> 1) & 3)) << 4); \
            cpa16(stg_ + STG_B_H + d_, Bh + (long long)row * ldb + kb + seg * 8); \
            if (PASSES == 3) cpa16(stg_ + STG_B_L + d_, Bl + (long long)row * ldb + kb + seg * 8); \
        } \
        CP_COMMIT(); \
    } while (0)

    ISSUE(0);
    ISSUE(1);

    for (int c = 0; c < NT; c++) {
        CP_WAIT1();
        __syncthreads();
        const u32 stg = smb + (u32)(c % NSTG) * STG_BYTES;

        #pragma unroll
        for (int kk = 0; kk < 2; kk++) {
            u32 ah[4][4], al[4][4];
            const int arow = wm * 64 + (lane & 15);
            const int aks  = kk * 2 + (lane >> 4);
            #pragma unroll
            for (int mt = 0; mt < 4; mt++) {
                const int ro = arow + mt * 16;
                const u32 off = (u32)ro * 64 + ((u32)(aks ^ ((ro >> 1) & 3)) << 4);
                LDM_X4(ah[mt], stg + STG_A_H + off);
                if (PASSES == 3) LDM_X4(al[mt], stg + STG_A_L + off);
            }
            const int brow0 = wn * 64 + ((lane >> 4) & 1) * 8 + (lane & 7);
            const int bks = kk * 2 + ((lane >> 3) & 1);
            #pragma unroll
            for (int np = 0; np < 4; np++) {
                const int ro = brow0 + np * 16;
                const u32 off = (u32)ro * 64 + ((u32)(bks ^ ((ro >> 1) & 3)) << 4);
                u32 th[4], tl[4];
                LDM_X4(th, stg + STG_B_H + off);
                if (PASSES == 3) LDM_X4(tl, stg + STG_B_L + off);
                #pragma unroll
                for (int mt = 0; mt < 4; mt++) {
                    MMA_BF16(acc[mt][np*2],   ah[mt], th[0], th[1]);
                    MMA_BF16(acc[mt][np*2+1], ah[mt], th[2], th[3]);
                    if (PASSES == 3) {
                        MMA_BF16(acc[mt][np*2],   ah[mt], tl[0], tl[1]);
                        MMA_BF16(acc[mt][np*2+1], ah[mt], tl[2], tl[3]);
                        MMA_BF16(acc[mt][np*2],   al[mt], th[0], th[1]);
                        MMA_BF16(acc[mt][np*2+1], al[mt], th[2], th[3]);
                    }
                }
            }
        }

        if (c + 2 < NT) { ISSUE(c + 2); } else { CP_COMMIT(); }
        __syncthreads();
    }
    #undef ISSUE

    // ---- epilogue: frag map rows lane>>2 (+8), cols (lane&3)*2 ----
    const int er = lane >> 2, ec = (lane & 3) * 2;
    #pragma unroll
    for (int mt = 0; mt < 4; mt++) {
        #pragma unroll
        for (int nt = 0; nt < 8; nt++) {
            const float* a4 = acc[mt][nt];
            const int row0 = m0 + wm * 64 + mt * 16 + er;
            const int col  = n0 + wn * 64 + nt * 8 + ec;
            float v00 = a4[0] * alpha, v01 = a4[1] * alpha;
            float v10 = a4[2] * alpha, v11 = a4[3] * alpha;
            if (BIAS) {
                const float bb0 = bias[col], bb1 = bias[col + 1];
                v00 += bb0; v01 += bb1; v10 += bb0; v11 += bb1;
            }
            if (RELU) {
                v00 = fmaxf(v00, 0.f); v01 = fmaxf(v01, 0.f);
                v10 = fmaxf(v10, 0.f); v11 = fmaxf(v11, 0.f);
            }
            if (MODE == 0) {
                float* C = Cf + coff;
                *(float2*)(C + (long long)row0 * ldc + col)       = make_float2(v00, v01);
                *(float2*)(C + (long long)(row0 + 8) * ldc + col) = make_float2(v10, v11);
            } else if (MODE == 1) {
                bf16 h0, l0, h1, l1;
                __nv_bfloat162 ph, pl;
                split2(v00, h0, l0); split2(v01, h1, l1);
                ph.x = h0; ph.y = h1; pl.x = l0; pl.y = l1;
                *(__nv_bfloat162*)(Ch + coff + (long long)row0 * ldc + col) = ph;
                *(__nv_bfloat162*)(Cl + coff + (long long)row0 * ldc + col) = pl;
                split2(v10, h0, l0); split2(v11, h1, l1);
                ph.x = h0; ph.y = h1; pl.x = l0; pl.y = l1;
                *(__nv_bfloat162*)(Ch + coff + (long long)(row0 + 8) * ldc + col) = ph;
                *(__nv_bfloat162*)(Cl + coff + (long long)(row0 + 8) * ldc + col) = pl;
            } else if (MODE == 2) {
                __nv_bfloat162 p0, p1;
                p0.x = __float2bfloat16(v00); p0.y = __float2bfloat16(v01);
                p1.x = __float2bfloat16(v10); p1.y = __float2bfloat16(v11);
                *(__nv_bfloat162*)(Ch + coff + (long long)row0 * ldc + col)       = p0;
                *(__nv_bfloat162*)(Ch + coff + (long long)(row0 + 8) * ldc + col) = p1;
            } else {
                // transposed: addr(e, token) = coff + (tok>>11)*(CD*CS) + (tok&2047) + e*CS
                const long long o0 = coff + (long long)(row0 >> 11) * ((long long)CD * CS) + (row0 & (CS - 1));
                const int r1 = row0 + 8;
                const long long o1 = coff + (long long)(r1 >> 11) * ((long long)CD * CS) + (r1 & (CS - 1));
                Ch[o0 + (long long)col * CS]       = __float2bfloat16(v00);
                Ch[o0 + (long long)(col + 1) * CS] = __float2bfloat16(v01);
                Ch[o1 + (long long)col * CS]       = __float2bfloat16(v10);
                Ch[o1 + (long long)(col + 1) * CS] = __float2bfloat16(v11);
            }
        }
    }
}

// ---------------- fp32 -> single hi plane ----------------
__global__ void __launch_bounds__(256)
conv1_k(const float* __restrict__ in, bf16* __restrict__ oh){
    const long long i = (long long)blockIdx.x * 256 + threadIdx.x;
    oh[i] = __float2bfloat16(in[i]);
}

// ---------------- fp32 [R,C] -> planes [C,R] (batched); TWO = both planes ----------------
template<bool TWO>
__global__ void __launch_bounds__(256)
transp_pack_k(const float* __restrict__ in, bf16* __restrict__ oh, bf16* __restrict__ ol,
              int R, int Cc, long long sIn, long long sOut){
    __shared__ float sm[32][33];
    const float* ip = in + (long long)blockIdx.z * sIn;
    bf16* oph = oh + (long long)blockIdx.z * sOut;
    bf16* opl = TWO ? (ol + (long long)blockIdx.z * sOut) : nullptr;
    const int x0 = blockIdx.x * 32, y0 = blockIdx.y * 32;
    const int tx = threadIdx.x & 31, ty = threadIdx.x >> 5;
    #pragma unroll
    for (int j = 0; j < 32; j += 8)
        sm[ty + j][tx] = ip[(long long)(y0 + ty + j) * Cc + x0 + tx];
    __syncthreads();
    #pragma unroll
    for (int j = 0; j < 32; j += 8) {
        const long long o = (long long)(x0 + ty + j) * R + y0 + tx;
        const float v = sm[tx][ty + j];
        if (TWO) { bf16 h, l; split2(v, h, l); oph[o] = h; opl[o] = l; }
        else       oph[o] = __float2bfloat16(v);
    }
}

// ---------------- softmax row 2048: bf16 in -> bf16 hi out ----------------
__global__ void __launch_bounds__(256)
softmax_k(const bf16* __restrict__ sc, bf16* __restrict__ oh){
    const long long row = blockIdx.x;
    const bf16* p = sc + row * (long long)CS;
    bf16* o = oh + row * (long long)CS;
    const int tid = threadIdx.x;
    __shared__ float sm[8];
    float v[8], mx = -3.4e38f;
    #pragma unroll
    for (int i = 0; i < 8; i++){ v[i] = __bfloat162float(p[tid + i*256]); mx = fmaxf(mx, v[i]); }
    #pragma unroll
    for (int w = 16; w; w >>= 1) mx = fmaxf(mx, __shfl_xor_sync(~0u, mx, w));
    if ((tid & 31) == 0) sm[tid >> 5] = mx;
    __syncthreads();
    if (tid < 32){
        float t = (tid < 8) ? sm[tid] : -3.4e38f;
        #pragma unroll
        for (int w = 4; w; w >>= 1) t = fmaxf(t, __shfl_xor_sync(~0u, t, w));
        if (tid == 0) sm[0] = t;
    }
    __syncthreads(); mx = sm[0]; __syncthreads();
    float s = 0.f;
    #pragma unroll
    for (int i = 0; i < 8; i++){ v[i] = __expf(v[i] - mx); s += v[i]; }
    #pragma unroll
    for (int w = 16; w; w >>= 1) s += __shfl_xor_sync(~0u, s, w);
    if ((tid & 31) == 0) sm[tid >> 5] = s;
    __syncthreads();
    if (tid < 32){
        float t = (tid < 8) ? sm[tid] : 0.f;
        #pragma unroll
        for (int w = 4; w; w >>= 1) t += __shfl_xor_sync(~0u, t, w);
        if (tid == 0) sm[0] = t;
    }
    __syncthreads();
    const float inv = 1.0f / sm[0];
    #pragma unroll
    for (int i = 0; i < 8; i++) o[tid + i*256] = __float2bfloat16(v[i] * inv);
}

// ---------------- out = LN(x+y)*g+b (+two-plane copy) ----------------
template<bool PK>
__global__ void __launch_bounds__(256)
add_ln_k(const float* __restrict__ x, const float* __restrict__ y,
         const float* __restrict__ g, const float* __restrict__ b,
         float* __restrict__ out, bf16* __restrict__ oh, bf16* __restrict__ ol){
    const long long row = blockIdx.x;
    const float* px = x + row * (long long)CD;
    const float* py = y + row * (long long)CD;
    float* po = out + row * (long long)CD;
    const int tid = threadIdx.x;
    __shared__ float sm[16];
    float v[4], s = 0.f, s2 = 0.f;
    #pragma unroll
    for (int i = 0; i < 4; i++){
        float t = px[tid + i*256] + py[tid + i*256];
        v[i] = t; s += t; s2 += t*t;
    }
    #pragma unroll
    for (int w = 16; w; w >>= 1){ s += __shfl_xor_sync(~0u, s, w); s2 += __shfl_xor_sync(~0u, s2, w); }
    if ((tid & 31) == 0){ sm[tid>>5] = s; sm[8 + (tid>>5)] = s2; }
    __syncthreads();
    if (tid < 32){
        float t = (tid < 8) ? sm[tid] : 0.f, t2 = (tid < 8) ? sm[8+tid] : 0.f;
        #pragma unroll
        for (int w = 4; w; w >>= 1){ t += __shfl_xor_sync(~0u, t, w); t2 += __shfl_xor_sync(~0u, t2, w); }
        if (tid == 0){ sm[0] = t; sm[8] = t2; }
    }
    __syncthreads();
    const float mean = sm[0] * (1.0f/CD);
    const float var  = sm[8] * (1.0f/CD) - mean*mean;
    const float rs = rsqrtf(var + 1e-5f);
    #pragma unroll
    for (int i = 0; i < 4; i++){
        const int c = tid + i*256;
        const float o = (v[i] - mean) * rs * g[c] + b[c];
        po[c] = o;
        if (PK) {
            bf16 h, l; split2(o, h, l);
            oh[row * (long long)CD + c] = h;
            ol[row * (long long)CD + c] = l;
        }
    }
}

// ---------------- kernel_launch ----------------
extern "C" void kernel_launch(void* const* d_in, const int* in_sizes, int n_in,
                              void* d_out, int out_size)
{
    const float* x  = (const float*)d_in[0];
    const float* Wq = (const float*)d_in[1];
    const float* Wk = (const float*)d_in[2];
    const float* Wv = (const float*)d_in[3];
    const float* Wo = (const float*)d_in[4];
    const float* bo = (const float*)d_in[5];
    const float* w1 = (const float*)d_in[6];
    const float* b1 = (const float*)d_in[7];
    const float* w2 = (const float*)d_in[8];
    const float* b2 = (const float*)d_in[9];
    const float* w3 = (const float*)d_in[10];
    const float* b3 = (const float*)d_in[11];
    const float* w4 = (const float*)d_in[12];
    const float* b4 = (const float*)d_in[13];
    const float* g1 = (const float*)d_in[14];
    const float* be1= (const float*)d_in[15];
    const float* g2 = (const float*)d_in[16];
    const float* be2= (const float*)d_in[17];
    float* out = (float*)d_out;

    bf16 *Xh,*Wqh,*Wkh,*Wvh,*Woh;
    bf16 *W1h,*W1l,*W2h,*W2l,*W3h,*W3l,*W4h,*W4l;
    bf16 *Qh,*Kh,*VTh,*SCb,*ATh,*ZCh;
    bf16 *Y1h,*Y1l,*Y2h,*Y2l,*ZNh,*ZNl;
    float *AO,*Z1;
    cudaGetSymbolAddress((void**)&Xh,  g_X_h_);
    cudaGetSymbolAddress((void**)&Wqh, g_Wq_h_);
    cudaGetSymbolAddress((void**)&Wkh, g_Wk_h_);
    cudaGetSymbolAddress((void**)&Wvh, g_Wv_h_);
    cudaGetSymbolAddress((void**)&Woh, g_Wo_h_);
    cudaGetSymbolAddress((void**)&W1h, g_W1_h_); cudaGetSymbolAddress((void**)&W1l, g_W1_l_);
    cudaGetSymbolAddress((void**)&W2h, g_W2_h_); cudaGetSymbolAddress((void**)&W2l, g_W2_l_);
    cudaGetSymbolAddress((void**)&W3h, g_W3_h_); cudaGetSymbolAddress((void**)&W3l, g_W3_l_);
    cudaGetSymbolAddress((void**)&W4h, g_W4_h_); cudaGetSymbolAddress((void**)&W4l, g_W4_l_);
    cudaGetSymbolAddress((void**)&Qh,  g_Q_h_);
    cudaGetSymbolAddress((void**)&Kh,  g_K_h_);
    cudaGetSymbolAddress((void**)&VTh, g_VT_h_);
    cudaGetSymbolAddress((void**)&SCb, g_SCb_h_);
    cudaGetSymbolAddress((void**)&ATh, g_AT_h_);
    cudaGetSymbolAddress((void**)&ZCh, g_ZC_h_);
    cudaGetSymbolAddress((void**)&Y1h, g_Y1_h_); cudaGetSymbolAddress((void**)&Y1l, g_Y1_l_);
    cudaGetSymbolAddress((void**)&Y2h, g_Y2_h_); cudaGetSymbolAddress((void**)&Y2l, g_Y2_l_);
    cudaGetSymbolAddress((void**)&ZNh, g_ZN_h_); cudaGetSymbolAddress((void**)&ZNl, g_ZN_l_);
    cudaGetSymbolAddress((void**)&AO, g_AO);
    cudaGetSymbolAddress((void**)&Z1, g_Z1);

    cudaFuncSetAttribute(tgemm<1,2,false,false>, cudaFuncAttributeMaxDynamicSharedMemorySize, TG_SMEM);
    cudaFuncSetAttribute(tgemm<1,3,false,false>, cudaFuncAttributeMaxDynamicSharedMemorySize, TG_SMEM);
    cudaFuncSetAttribute(tgemm<1,0,true,false>,  cudaFuncAttributeMaxDynamicSharedMemorySize, TG_SMEM);
    cudaFuncSetAttribute(tgemm<3,1,true,true>,   cudaFuncAttributeMaxDynamicSharedMemorySize, TG_SMEM);
    cudaFuncSetAttribute(tgemm<3,0,true,false>,  cudaFuncAttributeMaxDynamicSharedMemorySize, TG_SMEM);

    const int MT = CB * CS;                       // 8192
    const long long DD  = (long long)CD * CD;
    const long long HBD = (long long)CB * CS * CD;
    const long long SD  = (long long)CS * CD;
    const long long SS  = (long long)CS * CS;

    // ---- prep ----
    conv1_k<<<MT * CD / 256, 256>>>(x, Xh);
    transp_pack_k<false><<<dim3(32, 32, CH), 256>>>(Wq, Wqh, nullptr, CD, CD, DD, DD);
    transp_pack_k<false><<<dim3(32, 32, CH), 256>>>(Wk, Wkh, nullptr, CD, CD, DD, DD);
    transp_pack_k<false><<<dim3(32, 32, CH), 256>>>(Wv, Wvh, nullptr, CD, CD, DD, DD);
    transp_pack_k<false><<<dim3(32, 256, 1), 256>>>(Wo, Woh, nullptr, CH * CD, CD, 0, 0);
    transp_pack_k<true><<<dim3(128, 32, 1), 256>>>(w1, W1h, W1l, CD, CHID, 0, 0);
    transp_pack_k<true><<<dim3(128, 128, 1), 256>>>(w2, W2h, W2l, CHID, CHID, 0, 0);
    transp_pack_k<true><<<dim3(128, 128, 1), 256>>>(w3, W3h, W3l, CHID, CHID, 0, 0);
    transp_pack_k<true><<<dim3(32, 128, 1), 256>>>(w4, W4h, W4l, CHID, CD, 0, 0);

    // ---- QKV (bf16x1) ----
    {
        dim3 grid(CD / 256, MT / 128, CH);
        tgemm<1,2,false,false><<<grid, 256, TG_SMEM>>>(Xh, nullptr, Wqh, nullptr,
            nullptr, Qh, nullptr, nullptr, CD, CD, CD, CD, 0, DD, HBD, 0, 1, 1.0f);
        tgemm<1,2,false,false><<<grid, 256, TG_SMEM>>>(Xh, nullptr, Wkh, nullptr,
            nullptr, Kh, nullptr, nullptr, CD, CD, CD, CD, 0, DD, HBD, 0, 1, 1.0f);
        tgemm<1,3,false,false><<<grid, 256, TG_SMEM>>>(Xh, nullptr, Wvh, nullptr,
            nullptr, VTh, nullptr, nullptr, CD, CD, CD, 0, 0, DD, HBD, 0, 1, 1.0f);
    }
    // ---- scores = Q K^T / 32 (bf16x1, bf16 out) ----
    {
        dim3 grid(CS / 256, CS / 128, CH * CB);
        tgemm<1,2,false,false><<<grid, 256, TG_SMEM>>>(Qh, nullptr, Kh, nullptr,
            nullptr, SCb, nullptr, nullptr, CD, CD, CD, CS, SD, SD, SS, 0, 1, 0.03125f);
    }
    // ---- softmax ----
    softmax_k<<<CH * CB * CS, 256>>>(SCb, ATh);
    // ---- Z = attn @ V (bf16x1) -> head-concat hi ----
    {
        dim3 grid(CD / 256, CS / 128, CH * CB);
        tgemm<1,2,false,false><<<grid, 256, TG_SMEM>>>(ATh, nullptr, VTh, nullptr,
            nullptr, ZCh, nullptr, nullptr, CS, CS, CS, CH * CD, SS, (long long)CD * CS,
            (long long)CD, (long long)CS * CH * CD, CB, 1.0f);
    }
    // ---- attn_out = ZC @ Wo + bo (bf16x1) ----
    {
        dim3 grid(CD / 256, MT / 128, 1);
        tgemm<1,0,true,false><<<grid, 256, TG_SMEM>>>(ZCh, nullptr, Woh, nullptr,
            AO, nullptr, nullptr, bo, CH * CD, CH * CD, CH * CD, CD, 0, 0, 0, 0, 1, 1.0f);
    }
    // ---- Z1 = LN(x + attn_out) ----
    add_ln_k<true><<<MT, 256>>>(x, AO, g1, be1, Z1, ZNh, ZNl);
    // ---- FFN (bf16x3) ----
    {
        dim3 gh(CHID / 256, MT / 128, 1);
        tgemm<3,1,true,true><<<gh, 256, TG_SMEM>>>(ZNh, ZNl, W1h, W1l,
            nullptr, Y1h, Y1l, b1, CD, CD, CD, CHID, 0, 0, 0, 0, 1, 1.0f);
        tgemm<3,1,true,true><<<gh, 256, TG_SMEM>>>(Y1h, Y1l, W2h, W2l,
            nullptr, Y2h, Y2l, b2, CHID, CHID, CHID, CHID, 0, 0, 0, 0, 1, 1.0f);
        tgemm<3,1,true,true><<<gh, 256, TG_SMEM>>>(Y2h, Y2l, W3h, W3l,
            nullptr, Y1h, Y1l, b3, CHID, CHID, CHID, CHID, 0, 0, 0, 0, 1, 1.0f);
        dim3 g4(CD / 256, MT / 128, 1);
        tgemm<3,0,true,false><<<g4, 256, TG_SMEM>>>(Y1h, Y1l, W4h, W4l,
            AO, nullptr, nullptr, b4, CHID, CHID, CHID, CD, 0, 0, 0, 0, 1, 1.0f);
    }
    // ---- out = LN(Z1 + ffn_out) ----
    add_ln_k<false><<<MT, 256>>>(Z1, AO, g2, be2, out, nullptr, nullptr);
}

// round 12
// speedup vs baseline: 5.9832x; 1.2346x over previous
#include <cuda_runtime.h>
#include <cuda_fp16.h>
#include <math.h>

typedef unsigned int u32;
typedef unsigned long long u64;
typedef __half f16;

#define CB 4
#define CS 2048
#define CD 1024
#define CH 8
#define CHID 4096

// ---------------- scratch (device globals) ----------------
// FFN activations: TWO fp16 planes (hi = f16(x), lo = f16(x-hi)) for 2-pass split.
// Weights + attention tensors: hi plane only. All K-major, uint4 for 16B align.
#define DECL_PLANES(name, n) \
    __device__ uint4 name##_h_[(size_t)(n) / 8]; \
    __device__ uint4 name##_l_[(size_t)(n) / 8];
#define DECL_ONE(name, n) __device__ uint4 name##_h_[(size_t)(n) / 8];

DECL_ONE(g_X,  (size_t)CB*CS*CD)
DECL_ONE(g_Wq, (size_t)CH*CD*CD)
DECL_ONE(g_Wk, (size_t)CH*CD*CD)
DECL_ONE(g_Wv, (size_t)CH*CD*CD)
DECL_ONE(g_Wo, (size_t)CD*CH*CD)
DECL_ONE(g_W1, (size_t)CHID*CD)
DECL_ONE(g_W2, (size_t)CHID*CHID)
DECL_ONE(g_W3, (size_t)CHID*CHID)
DECL_ONE(g_W4, (size_t)CD*CHID)
DECL_ONE(g_Q,  (size_t)CH*CB*CS*CD)     // [(h,b)][s][d]
DECL_ONE(g_K,  (size_t)CH*CB*CS*CD)
DECL_ONE(g_VT, (size_t)CH*CB*CD*CS)     // [h][b][e][t]
DECL_ONE(g_SCb,(size_t)CH*CB*CS*CS)     // scores f16
DECL_ONE(g_AT, (size_t)CH*CB*CS*CS)     // attn f16
DECL_ONE(g_ZC, (size_t)CB*CS*CH*CD)     // head-concat f16
DECL_PLANES(g_Y1, (size_t)CB*CS*CHID)
DECL_PLANES(g_Y2, (size_t)CB*CS*CHID)
DECL_PLANES(g_ZN, (size_t)CB*CS*CD)
__device__ float g_AO[(size_t)CB*CS*CD];
__device__ float g_Z1[(size_t)CB*CS*CD];

// ---------------- helpers ----------------
__device__ __forceinline__ u32 smem_u32(const void* p){
    u32 a; asm("{ .reg .u64 t; cvta.to.shared.u64 t, %1; cvt.u32.u64 %0, t; }":"=r"(a):"l"(p)); return a;
}
__device__ __forceinline__ void split2(float v, f16& h, f16& l){
    h = __float2half(v);
    l = __float2half(v - __half2float(h));
}
__device__ __forceinline__ void cpa16(u32 dst, const void* src){
    asm volatile("cp.async.cg.shared.global [%0], [%1], 16;" :: "r"(dst), "l"(src));
}
#define CP_COMMIT() asm volatile("cp.async.commit_group;" ::: "memory")
#define CP_WAIT1()  asm volatile("cp.async.wait_group 1;" ::: "memory")

#define LDM_X4(r, a) asm volatile( \
    "ldmatrix.sync.aligned.m8n8.x4.shared.b16 {%0,%1,%2,%3}, [%4];" \
    : "=r"((r)[0]),"=r"((r)[1]),"=r"((r)[2]),"=r"((r)[3]) : "r"(a))

#define MMA_F16(c, a, b0v, b1v) asm volatile( \
    "mma.sync.aligned.m16n8k16.row.col.f32.f16.f16.f32 " \
    "{%0,%1,%2,%3},{%4,%5,%6,%7},{%8,%9},{%0,%1,%2,%3};" \
    : "+f"((c)[0]),"+f"((c)[1]),"+f"((c)[2]),"+f"((c)[3]) \
    : "r"((a)[0]),"r"((a)[1]),"r"((a)[2]),"r"((a)[3]), "r"(b0v),"r"(b1v))

// ---------------- mma.sync GEMM: CTA 128x256, warp 64x64, K-chunk 32 ----------------
// 3-stage cp.async pipeline. PASSES: 1 = Ah*B; 2 = (Ah + Al)*B (A split, fp16).
// MODE: 0 fp32 out; 1 two-plane out; 2 single-plane row-major; 3 single-plane transposed.
#define STG_A_H 0
#define STG_A_L 8192
#define STG_B_H 16384
#define STG_BYTES 49152
#define NSTG 3
#define TG_SMEM (NSTG * STG_BYTES)

template<int PASSES, int MODE, bool BIAS, bool RELU>
__global__ void __launch_bounds__(256, 1)
tgemm(const f16* __restrict__ Ah, const f16* __restrict__ Al,
      const f16* __restrict__ Bh,
      float* __restrict__ Cf, f16* __restrict__ Ch, f16* __restrict__ Cl,
      const float* __restrict__ bias,
      int K, int lda, int ldb, int ldc,
      long long sA, long long sB, long long cs1, long long cs2, int cdiv,
      float alpha)
{
    extern __shared__ __align__(16) char smem[];
    const u32 smb = smem_u32(smem);

    const int tid = threadIdx.x, lane = tid & 31, wid = tid >> 5;
    const int wm = wid >> 2, wn = wid & 3;                    // 2m x 4n warps, 64x64 each
    const int z = blockIdx.z, m0 = blockIdx.y * 128, n0 = blockIdx.x * 256;

    Ah += (long long)z * sA + (long long)m0 * lda;
    Bh += (long long)z * sB + (long long)n0 * ldb;
    if (PASSES == 2) Al += (long long)z * sA + (long long)m0 * lda;
    const long long coff = (long long)(z / cdiv) * cs1 + (long long)(z % cdiv) * cs2;

    float acc[4][8][4];
    #pragma unroll
    for (int i = 0; i < 4; i++)
        #pragma unroll
        for (int j = 0; j < 8; j++)
            #pragma unroll
            for (int q = 0; q < 4; q++) acc[i][j][q] = 0.f;

    const int NT = K >> 5;

    #define ISSUE(cc) do { \
        const int kb = (cc) * 32; \
        const u32 stg_ = smb + (u32)((cc) % NSTG) * STG_BYTES; \
        _Pragma("unroll") \
        for (int t2 = 0; t2 < 2; t2++) { \
            const int task = t2 * 256 + tid; \
            const int row = task >> 2, seg = task & 3; \
            const u32 d_ = (u32)row * 64 + ((u32)(seg ^ ((row >> 1) & 3)) << 4); \
            cpa16(stg_ + STG_A_H + d_, Ah + (long long)row * lda + kb + seg * 8); \
            if (PASSES == 2) cpa16(stg_ + STG_A_L + d_, Al + (long long)row * lda + kb + seg * 8); \
        } \
        _Pragma("unroll") \
        for (int t4 = 0; t4 < 4; t4++) { \
            const int task = t4 * 256 + tid; \
            const int row = task >> 2, seg = task & 3; \
            const u32 d_ = (u32)row * 64 + ((u32)(seg ^ ((row >> 1) & 3)) << 4); \
            cpa16(stg_ + STG_B_H + d_, Bh + (long long)row * ldb + kb + seg * 8); \
        } \
        CP_COMMIT(); \
    } while (0)

    ISSUE(0);
    ISSUE(1);

    for (int c = 0; c < NT; c++) {
        CP_WAIT1();
        __syncthreads();
        const u32 stg = smb + (u32)(c % NSTG) * STG_BYTES;

        #pragma unroll
        for (int kk = 0; kk < 2; kk++) {
            u32 ah[4][4], al[4][4];
            const int arow = wm * 64 + (lane & 15);
            const int aks  = kk * 2 + (lane >> 4);
            #pragma unroll
            for (int mt = 0; mt < 4; mt++) {
                const int ro = arow + mt * 16;
                const u32 off = (u32)ro * 64 + ((u32)(aks ^ ((ro >> 1) & 3)) << 4);
                LDM_X4(ah[mt], stg + STG_A_H + off);
                if (PASSES == 2) LDM_X4(al[mt], stg + STG_A_L + off);
            }
            const int brow0 = wn * 64 + ((lane >> 4) & 1) * 8 + (lane & 7);
            const int bks = kk * 2 + ((lane >> 3) & 1);
            #pragma unroll
            for (int np = 0; np < 4; np++) {
                const int ro = brow0 + np * 16;
                const u32 off = (u32)ro * 64 + ((u32)(bks ^ ((ro >> 1) & 3)) << 4);
                u32 th[4];
                LDM_X4(th, stg + STG_B_H + off);
                #pragma unroll
                for (int mt = 0; mt < 4; mt++) {
                    MMA_F16(acc[mt][np*2],   ah[mt], th[0], th[1]);
                    MMA_F16(acc[mt][np*2+1], ah[mt], th[2], th[3]);
                    if (PASSES == 2) {
                        MMA_F16(acc[mt][np*2],   al[mt], th[0], th[1]);
                        MMA_F16(acc[mt][np*2+1], al[mt], th[2], th[3]);
                    }
                }
            }
        }

        if (c + 2 < NT) { ISSUE(c + 2); } else { CP_COMMIT(); }
        __syncthreads();
    }
    #undef ISSUE

    // ---- epilogue: frag map rows lane>>2 (+8), cols (lane&3)*2 ----
    const int er = lane >> 2, ec = (lane & 3) * 2;
    #pragma unroll
    for (int mt = 0; mt < 4; mt++) {
        #pragma unroll
        for (int nt = 0; nt < 8; nt++) {
            const float* a4 = acc[mt][nt];
            const int row0 = m0 + wm * 64 + mt * 16 + er;
            const int col  = n0 + wn * 64 + nt * 8 + ec;
            float v00 = a4[0] * alpha, v01 = a4[1] * alpha;
            float v10 = a4[2] * alpha, v11 = a4[3] * alpha;
            if (BIAS) {
                const float bb0 = bias[col], bb1 = bias[col + 1];
                v00 += bb0; v01 += bb1; v10 += bb0; v11 += bb1;
            }
            if (RELU) {
                v00 = fmaxf(v00, 0.f); v01 = fmaxf(v01, 0.f);
                v10 = fmaxf(v10, 0.f); v11 = fmaxf(v11, 0.f);
            }
            if (MODE == 0) {
                float* C = Cf + coff;
                *(float2*)(C + (long long)row0 * ldc + col)       = make_float2(v00, v01);
                *(float2*)(C + (long long)(row0 + 8) * ldc + col) = make_float2(v10, v11);
            } else if (MODE == 1) {
                f16 h0, l0, h1, l1;
                __half2 ph, pl;
                split2(v00, h0, l0); split2(v01, h1, l1);
                ph.x = h0; ph.y = h1; pl.x = l0; pl.y = l1;
                *(__half2*)(Ch + coff + (long long)row0 * ldc + col) = ph;
                *(__half2*)(Cl + coff + (long long)row0 * ldc + col) = pl;
                split2(v10, h0, l0); split2(v11, h1, l1);
                ph.x = h0; ph.y = h1; pl.x = l0; pl.y = l1;
                *(__half2*)(Ch + coff + (long long)(row0 + 8) * ldc + col) = ph;
                *(__half2*)(Cl + coff + (long long)(row0 + 8) * ldc + col) = pl;
            } else if (MODE == 2) {
                __half2 p0, p1;
                p0.x = __float2half(v00); p0.y = __float2half(v01);
                p1.x = __float2half(v10); p1.y = __float2half(v11);
                *(__half2*)(Ch + coff + (long long)row0 * ldc + col)       = p0;
                *(__half2*)(Ch + coff + (long long)(row0 + 8) * ldc + col) = p1;
            } else {
                // transposed: addr(e, token) = coff + (tok>>11)*(CD*CS) + (tok&2047) + e*CS
                const long long o0 = coff + (long long)(row0 >> 11) * ((long long)CD * CS) + (row0 & (CS - 1));
                const int r1 = row0 + 8;
                const long long o1 = coff + (long long)(r1 >> 11) * ((long long)CD * CS) + (r1 & (CS - 1));
                Ch[o0 + (long long)col * CS]       = __float2half(v00);
                Ch[o0 + (long long)(col + 1) * CS] = __float2half(v01);
                Ch[o1 + (long long)col * CS]       = __float2half(v10);
                Ch[o1 + (long long)(col + 1) * CS] = __float2half(v11);
            }
        }
    }
}

// ---------------- fp32 -> single hi plane ----------------
__global__ void __launch_bounds__(256)
conv1_k(const float* __restrict__ in, f16* __restrict__ oh){
    const long long i = (long long)blockIdx.x * 256 + threadIdx.x;
    oh[i] = __float2half(in[i]);
}

// ---------------- fp32 [R,C] -> hi plane [C,R] (batched) ----------------
__global__ void __launch_bounds__(256)
transp_pack_k(const float* __restrict__ in, f16* __restrict__ oh,
              int R, int Cc, long long sIn, long long sOut){
    __shared__ float sm[32][33];
    const float* ip = in + (long long)blockIdx.z * sIn;
    f16* oph = oh + (long long)blockIdx.z * sOut;
    const int x0 = blockIdx.x * 32, y0 = blockIdx.y * 32;
    const int tx = threadIdx.x & 31, ty = threadIdx.x >> 5;
    #pragma unroll
    for (int j = 0; j < 32; j += 8)
        sm[ty + j][tx] = ip[(long long)(y0 + ty + j) * Cc + x0 + tx];
    __syncthreads();
    #pragma unroll
    for (int j = 0; j < 32; j += 8)
        oph[(long long)(x0 + ty + j) * R + y0 + tx] = __float2half(sm[tx][ty + j]);
}

// ---------------- softmax row 2048: f16 in -> f16 out ----------------
__global__ void __launch_bounds__(256)
softmax_k(const f16* __restrict__ sc, f16* __restrict__ oh){
    const long long row = blockIdx.x;
    const f16* p = sc + row * (long long)CS;
    f16* o = oh + row * (long long)CS;
    const int tid = threadIdx.x;
    __shared__ float sm[8];
    float v[8], mx = -3.4e38f;
    #pragma unroll
    for (int i = 0; i < 8; i++){ v[i] = __half2float(p[tid + i*256]); mx = fmaxf(mx, v[i]); }
    #pragma unroll
    for (int w = 16; w; w >>= 1) mx = fmaxf(mx, __shfl_xor_sync(~0u, mx, w));
    if ((tid & 31) == 0) sm[tid >> 5] = mx;
    __syncthreads();
    if (tid < 32){
        float t = (tid < 8) ? sm[tid] : -3.4e38f;
        #pragma unroll
        for (int w = 4; w; w >>= 1) t = fmaxf(t, __shfl_xor_sync(~0u, t, w));
        if (tid == 0) sm[0] = t;
    }
    __syncthreads(); mx = sm[0]; __syncthreads();
    float s = 0.f;
    #pragma unroll
    for (int i = 0; i < 8; i++){ v[i] = __expf(v[i] - mx); s += v[i]; }
    #pragma unroll
    for (int w = 16; w; w >>= 1) s += __shfl_xor_sync(~0u, s, w);
    if ((tid & 31) == 0) sm[tid >> 5] = s;
    __syncthreads();
    if (tid < 32){
        float t = (tid < 8) ? sm[tid] : 0.f;
        #pragma unroll
        for (int w = 4; w; w >>= 1) t += __shfl_xor_sync(~0u, t, w);
        if (tid == 0) sm[0] = t;
    }
    __syncthreads();
    const float inv = 1.0f / sm[0];
    #pragma unroll
    for (int i = 0; i < 8; i++) o[tid + i*256] = __float2half(v[i] * inv);
}

// ---------------- out = LN(x+y)*g+b (+two-plane copy) ----------------
template<bool PK>
__global__ void __launch_bounds__(256)
add_ln_k(const float* __restrict__ x, const float* __restrict__ y,
         const float* __restrict__ g, const float* __restrict__ b,
         float* __restrict__ out, f16* __restrict__ oh, f16* __restrict__ ol){
    const long long row = blockIdx.x;
    const float* px = x + row * (long long)CD;
    const float* py = y + row * (long long)CD;
    float* po = out + row * (long long)CD;
    const int tid = threadIdx.x;
    __shared__ float sm[16];
    float v[4], s = 0.f, s2 = 0.f;
    #pragma unroll
    for (int i = 0; i < 4; i++){
        float t = px[tid + i*256] + py[tid + i*256];
        v[i] = t; s += t; s2 += t*t;
    }
    #pragma unroll
    for (int w = 16; w; w >>= 1){ s += __shfl_xor_sync(~0u, s, w); s2 += __shfl_xor_sync(~0u, s2, w); }
    if ((tid & 31) == 0){ sm[tid>>5] = s; sm[8 + (tid>>5)] = s2; }
    __syncthreads();
    if (tid < 32){
        float t = (tid < 8) ? sm[tid] : 0.f, t2 = (tid < 8) ? sm[8+tid] : 0.f;
        #pragma unroll
        for (int w = 4; w; w >>= 1){ t += __shfl_xor_sync(~0u, t, w); t2 += __shfl_xor_sync(~0u, t2, w); }
        if (tid == 0){ sm[0] = t; sm[8] = t2; }
    }
    __syncthreads();
    const float mean = sm[0] * (1.0f/CD);
    const float var  = sm[8] * (1.0f/CD) - mean*mean;
    const float rs = rsqrtf(var + 1e-5f);
    #pragma unroll
    for (int i = 0; i < 4; i++){
        const int c = tid + i*256;
        const float o = (v[i] - mean) * rs * g[c] + b[c];
        po[c] = o;
        if (PK) {
            f16 h, l; split2(o, h, l);
            oh[row * (long long)CD + c] = h;
            ol[row * (long long)CD + c] = l;
        }
    }
}

// ---------------- kernel_launch ----------------
extern "C" void kernel_launch(void* const* d_in, const int* in_sizes, int n_in,
                              void* d_out, int out_size)
{
    const float* x  = (const float*)d_in[0];
    const float* Wq = (const float*)d_in[1];
    const float* Wk = (const float*)d_in[2];
    const float* Wv = (const float*)d_in[3];
    const float* Wo = (const float*)d_in[4];
    const float* bo = (const float*)d_in[5];
    const float* w1 = (const float*)d_in[6];
    const float* b1 = (const float*)d_in[7];
    const float* w2 = (const float*)d_in[8];
    const float* b2 = (const float*)d_in[9];
    const float* w3 = (const float*)d_in[10];
    const float* b3 = (const float*)d_in[11];
    const float* w4 = (const float*)d_in[12];
    const float* b4 = (const float*)d_in[13];
    const float* g1 = (const float*)d_in[14];
    const float* be1= (const float*)d_in[15];
    const float* g2 = (const float*)d_in[16];
    const float* be2= (const float*)d_in[17];
    float* out = (float*)d_out;

    f16 *Xh,*Wqh,*Wkh,*Wvh,*Woh,*W1h,*W2h,*W3h,*W4h;
    f16 *Qh,*Kh,*VTh,*SCb,*ATh,*ZCh;
    f16 *Y1h,*Y1l,*Y2h,*Y2l,*ZNh,*ZNl;
    float *AO,*Z1;
    cudaGetSymbolAddress((void**)&Xh,  g_X_h_);
    cudaGetSymbolAddress((void**)&Wqh, g_Wq_h_);
    cudaGetSymbolAddress((void**)&Wkh, g_Wk_h_);
    cudaGetSymbolAddress((void**)&Wvh, g_Wv_h_);
    cudaGetSymbolAddress((void**)&Woh, g_Wo_h_);
    cudaGetSymbolAddress((void**)&W1h, g_W1_h_);
    cudaGetSymbolAddress((void**)&W2h, g_W2_h_);
    cudaGetSymbolAddress((void**)&W3h, g_W3_h_);
    cudaGetSymbolAddress((void**)&W4h, g_W4_h_);
    cudaGetSymbolAddress((void**)&Qh,  g_Q_h_);
    cudaGetSymbolAddress((void**)&Kh,  g_K_h_);
    cudaGetSymbolAddress((void**)&VTh, g_VT_h_);
    cudaGetSymbolAddress((void**)&SCb, g_SCb_h_);
    cudaGetSymbolAddress((void**)&ATh, g_AT_h_);
    cudaGetSymbolAddress((void**)&ZCh, g_ZC_h_);
    cudaGetSymbolAddress((void**)&Y1h, g_Y1_h_); cudaGetSymbolAddress((void**)&Y1l, g_Y1_l_);
    cudaGetSymbolAddress((void**)&Y2h, g_Y2_h_); cudaGetSymbolAddress((void**)&Y2l, g_Y2_l_);
    cudaGetSymbolAddress((void**)&ZNh, g_ZN_h_); cudaGetSymbolAddress((void**)&ZNl, g_ZN_l_);
    cudaGetSymbolAddress((void**)&AO, g_AO);
    cudaGetSymbolAddress((void**)&Z1, g_Z1);

    cudaFuncSetAttribute(tgemm<1,2,false,false>, cudaFuncAttributeMaxDynamicSharedMemorySize, TG_SMEM);
    cudaFuncSetAttribute(tgemm<1,3,false,false>, cudaFuncAttributeMaxDynamicSharedMemorySize, TG_SMEM);
    cudaFuncSetAttribute(tgemm<1,0,true,false>,  cudaFuncAttributeMaxDynamicSharedMemorySize, TG_SMEM);
    cudaFuncSetAttribute(tgemm<2,1,true,true>,   cudaFuncAttributeMaxDynamicSharedMemorySize, TG_SMEM);
    cudaFuncSetAttribute(tgemm<2,0,true,false>,  cudaFuncAttributeMaxDynamicSharedMemorySize, TG_SMEM);

    const int MT = CB * CS;                       // 8192
    const long long DD  = (long long)CD * CD;
    const long long HBD = (long long)CB * CS * CD;
    const long long SD  = (long long)CS * CD;
    const long long SS  = (long long)CS * CS;

    // ---- prep ----
    conv1_k<<<MT * CD / 256, 256>>>(x, Xh);
    transp_pack_k<<<dim3(32, 32, CH), 256>>>(Wq, Wqh, CD, CD, DD, DD);
    transp_pack_k<<<dim3(32, 32, CH), 256>>>(Wk, Wkh, CD, CD, DD, DD);
    transp_pack_k<<<dim3(32, 32, CH), 256>>>(Wv, Wvh, CD, CD, DD, DD);
    transp_pack_k<<<dim3(32, 256, 1), 256>>>(Wo, Woh, CH * CD, CD, 0, 0);
    transp_pack_k<<<dim3(128, 32, 1), 256>>>(w1, W1h, CD, CHID, 0, 0);
    transp_pack_k<<<dim3(128, 128, 1), 256>>>(w2, W2h, CHID, CHID, 0, 0);
    transp_pack_k<<<dim3(128, 128, 1), 256>>>(w3, W3h, CHID, CHID, 0, 0);
    transp_pack_k<<<dim3(32, 128, 1), 256>>>(w4, W4h, CHID, CD, 0, 0);

    // ---- QKV (fp16 1-pass) ----
    {
        dim3 grid(CD / 256, MT / 128, CH);
        tgemm<1,2,false,false><<<grid, 256, TG_SMEM>>>(Xh, nullptr, Wqh,
            nullptr, Qh, nullptr, nullptr, CD, CD, CD, CD, 0, DD, HBD, 0, 1, 1.0f);
        tgemm<1,2,false,false><<<grid, 256, TG_SMEM>>>(Xh, nullptr, Wkh,
            nullptr, Kh, nullptr, nullptr, CD, CD, CD, CD, 0, DD, HBD, 0, 1, 1.0f);
        tgemm<1,3,false,false><<<grid, 256, TG_SMEM>>>(Xh, nullptr, Wvh,
            nullptr, VTh, nullptr, nullptr, CD, CD, CD, 0, 0, DD, HBD, 0, 1, 1.0f);
    }
    // ---- scores = Q K^T / 32 (fp16 1-pass) ----
    {
        dim3 grid(CS / 256, CS / 128, CH * CB);
        tgemm<1,2,false,false><<<grid, 256, TG_SMEM>>>(Qh, nullptr, Kh,
            nullptr, SCb, nullptr, nullptr, CD, CD, CD, CS, SD, SD, SS, 0, 1, 0.03125f);
    }
    // ---- softmax ----
    softmax_k<<<CH * CB * CS, 256>>>(SCb, ATh);
    // ---- Z = attn @ V (fp16 1-pass) -> head-concat ----
    {
        dim3 grid(CD / 256, CS / 128, CH * CB);
        tgemm<1,2,false,false><<<grid, 256, TG_SMEM>>>(ATh, nullptr, VTh,
            nullptr, ZCh, nullptr, nullptr, CS, CS, CS, CH * CD, SS, (long long)CD * CS,
            (long long)CD, (long long)CS * CH * CD, CB, 1.0f);
    }
    // ---- attn_out = ZC @ Wo + bo (fp16 1-pass) ----
    {
        dim3 grid(CD / 256, MT / 128, 1);
        tgemm<1,0,true,false><<<grid, 256, TG_SMEM>>>(ZCh, nullptr, Woh,
            AO, nullptr, nullptr, bo, CH * CD, CH * CD, CH * CD, CD, 0, 0, 0, 0, 1, 1.0f);
    }
    // ---- Z1 = LN(x + attn_out) ----
    add_ln_k<true><<<MT, 256>>>(x, AO, g1, be1, Z1, ZNh, ZNl);
    // ---- FFN (fp16 2-pass A-split) ----
    {
        dim3 gh(CHID / 256, MT / 128, 1);
        tgemm<2,1,true,true><<<gh, 256, TG_SMEM>>>(ZNh, ZNl, W1h,
            nullptr, Y1h, Y1l, b1, CD, CD, CD, CHID, 0, 0, 0, 0, 1, 1.0f);
        tgemm<2,1,true,true><<<gh, 256, TG_SMEM>>>(Y1h, Y1l, W2h,
            nullptr, Y2h, Y2l, b2, CHID, CHID, CHID, CHID, 0, 0, 0, 0, 1, 1.0f);
        tgemm<2,1,true,true><<<gh, 256, TG_SMEM>>>(Y2h, Y2l, W3h,
            nullptr, Y1h, Y1l, b3, CHID, CHID, CHID, CHID, 0, 0, 0, 0, 1, 1.0f);
        dim3 g4(CD / 256, MT / 128, 1);
        tgemm<2,0,true,false><<<g4, 256, TG_SMEM>>>(Y1h, Y1l, W4h,
            AO, nullptr, nullptr, b4, CHID, CHID, CHID, CD, 0, 0, 0, 0, 1, 1.0f);
    }
    // ---- out = LN(Z1 + ffn_out) ----
    add_ln_k<false><<<MT, 256>>>(Z1, AO, g2, be2, out, nullptr, nullptr);
}